// round 1
// baseline (speedup 1.0000x reference)
#include <cuda_runtime.h>
#include <cuda_bf16.h>
#include <mma.h>
#include <math.h>

using namespace nvcuda;

// ---------------- problem constants ----------------
#define Bb   2
#define Lq   1024
#define Vn   1024
#define Hh   4096
#define NHh  32
#define HDd  128
#define Mrows (Bb*Lq)          // 2048 (also B*Vn)
#define QSCALE 0.08838834764831845f   // 1/sqrt(128)

// ---------------- scratch (device globals; no allocations allowed) ----------
__device__ float g_Q  [(size_t)Mrows*Hh];   // Q rows [B*L, H], pre-scaled
__device__ float g_K  [(size_t)Mrows*Hh];   // K rows [B*V, H]
__device__ float g_Vt [(size_t)Bb*Hh*Vn];   // V transposed: [(b*H + h*128+d) , v]
__device__ float g_ctx[(size_t)Mrows*Hh];   // attention output [B*L, H]
__device__ float g_X  [(size_t)Mrows*Hh];   // pre-LN (hidden + attn_out)

// ---------------- WMMA types (tf32 m16n16k8) --------------------------------
typedef wmma::fragment<wmma::matrix_a, 16, 16, 8, wmma::precision::tf32, wmma::row_major> AFrag;
typedef wmma::fragment<wmma::matrix_b, 16, 16, 8, wmma::precision::tf32, wmma::col_major> BFrag;
typedef wmma::fragment<wmma::accumulator, 16, 16, 8, float>                               CFrag;

__device__ __forceinline__ float tf32r(float x) { return wmma::__float_to_tf32(x); }

// ============================================================================
// GEMM: out = (A[M,K] @ W[N,K]^T + bias) * scale  (+ resid)  (M=2048,N=K=4096)
// mode 0: row-major store        (Q/K projections; scale folds 1/sqrt(HD) for Q)
// mode 1: transposed store to Vt (V projection)
// mode 2: row-major store + residual (O projection)
// CTA tile 128x128, BK=16, 8 warps (4x2), warp tile 32x64, double-buffered smem
// ============================================================================
#define BM 128
#define BN 128
#define BK 16
#define LDA_S 20                 // BK + 4 pad (keeps float4 alignment)
#define STG_LD 20                // epilogue staging ld (multiple of 4)

#define GEMM_SMEM ((4*BM*LDA_S + 8*16*STG_LD) * 4)

__global__ __launch_bounds__(256) void gemm_tf32(
    const float* __restrict__ A, const float* __restrict__ W,
    const float* __restrict__ bias, const float* __restrict__ resid,
    float* __restrict__ out, float scale, int mode)
{
    extern __shared__ float sm[];
    float* As = sm;                          // 2 * BM * LDA_S
    float* Bs = sm + 2*BM*LDA_S;             // 2 * BN * LDA_S
    float* st = sm + 4*BM*LDA_S;             // 8 * 16 * STG_LD

    const int tid  = threadIdx.x;
    const int warp = tid >> 5, lane = tid & 31;
    const int wm = warp >> 1;                // 0..3  -> 32 rows
    const int wn = warp & 1;                 // 0..1  -> 64 cols
    const int bm = blockIdx.y, bn = blockIdx.x;

    CFrag acc[2][4];
    #pragma unroll
    for (int i = 0; i < 2; i++)
        #pragma unroll
        for (int j = 0; j < 4; j++) wmma::fill_fragment(acc[i][j], 0.0f);

    const float* Ab = A + (size_t)(bm*BM) * Hh;
    const float* Wb = W + (size_t)(bn*BN) * Hh;
    const int f0 = tid * 2;                  // two float4 per thread per tile

    float4 ra[2], rb[2];

    // prologue: tile 0
    #pragma unroll
    for (int i = 0; i < 2; i++) {
        int f = f0 + i, row = f >> 2, c = (f & 3) * 4;
        ra[i] = *(const float4*)(Ab + (size_t)row * Hh + c);
        rb[i] = *(const float4*)(Wb + (size_t)row * Hh + c);
    }
    #pragma unroll
    for (int i = 0; i < 2; i++) {
        int f = f0 + i, row = f >> 2, c = (f & 3) * 4;
        float4 v = ra[i];
        v.x = tf32r(v.x); v.y = tf32r(v.y); v.z = tf32r(v.z); v.w = tf32r(v.w);
        *(float4*)(As + row * LDA_S + c) = v;
        v = rb[i];
        v.x = tf32r(v.x); v.y = tf32r(v.y); v.z = tf32r(v.z); v.w = tf32r(v.w);
        *(float4*)(Bs + row * LDA_S + c) = v;
    }
    __syncthreads();

    const int nk = Hh / BK;                  // 256
    #pragma unroll 1
    for (int kt = 0; kt < nk; kt++) {
        const int cur = kt & 1, nxt = cur ^ 1;
        if (kt + 1 < nk) {
            int k0 = (kt + 1) * BK;
            #pragma unroll
            for (int i = 0; i < 2; i++) {
                int f = f0 + i, row = f >> 2, c = (f & 3) * 4;
                ra[i] = *(const float4*)(Ab + (size_t)row * Hh + k0 + c);
                rb[i] = *(const float4*)(Wb + (size_t)row * Hh + k0 + c);
            }
        }
        #pragma unroll
        for (int kk = 0; kk < BK; kk += 8) {
            AFrag fa[2]; BFrag fb[4];
            #pragma unroll
            for (int i = 0; i < 2; i++)
                wmma::load_matrix_sync(fa[i], As + cur*BM*LDA_S + (wm*32 + i*16)*LDA_S + kk, LDA_S);
            #pragma unroll
            for (int j = 0; j < 4; j++)
                wmma::load_matrix_sync(fb[j], Bs + cur*BN*LDA_S + (wn*64 + j*16)*LDA_S + kk, LDA_S);
            #pragma unroll
            for (int i = 0; i < 2; i++)
                #pragma unroll
                for (int j = 0; j < 4; j++)
                    wmma::mma_sync(acc[i][j], fa[i], fb[j], acc[i][j]);
        }
        if (kt + 1 < nk) {
            #pragma unroll
            for (int i = 0; i < 2; i++) {
                int f = f0 + i, row = f >> 2, c = (f & 3) * 4;
                float4 v = ra[i];
                v.x = tf32r(v.x); v.y = tf32r(v.y); v.z = tf32r(v.z); v.w = tf32r(v.w);
                *(float4*)(As + nxt*BM*LDA_S + row * LDA_S + c) = v;
                v = rb[i];
                v.x = tf32r(v.x); v.y = tf32r(v.y); v.z = tf32r(v.z); v.w = tf32r(v.w);
                *(float4*)(Bs + nxt*BN*LDA_S + row * LDA_S + c) = v;
            }
        }
        __syncthreads();
    }

    // ---- epilogue through smem staging (handles bias/scale/resid/transpose) ----
    float* stw = st + warp * 16 * STG_LD;
    #pragma unroll
    for (int i = 0; i < 2; i++) {
        #pragma unroll
        for (int j = 0; j < 4; j++) {
            wmma::store_matrix_sync(stw, acc[i][j], STG_LD, wmma::mem_row_major);
            __syncwarp();
            const int m0 = bm*BM + wm*32 + i*16;
            const int n0 = bn*BN + wn*64 + j*16;
            #pragma unroll
            for (int e = lane; e < 256; e += 32) {
                int r = e >> 4, c = e & 15;
                int m = m0 + r, n = n0 + c;
                float v = (stw[r * STG_LD + c] + bias[n]) * scale;
                if (mode == 0) {
                    out[(size_t)m * Hh + n] = v;
                } else if (mode == 1) {
                    // Vt[(b*H + n) * Vn + v] ; m = b*Vn + vrow
                    int b = m >> 10, vr = m & 1023;
                    out[((size_t)b * Hh + n) * Vn + vr] = v;
                } else {
                    out[(size_t)m * Hh + n] = v + resid[(size_t)m * Hh + n];
                }
            }
            __syncwarp();
        }
    }
}

// ============================================================================
// Flash cross-attention: per CTA one head (b,h) x 64 query rows; loop over
// 16 kv-tiles of 64. tf32 wmma for S=QK^T and PV; fp32 online softmax in smem.
// ============================================================================
#define BQt 64
#define BVt 64
#define LQD 132          // HD + 4
#define LVD 68           // BVt + 4
// floats: Qs 64*132 + KV 128*68 + Ss 64*68 + PVs 64*132 + Os 64*132 + 3*64  (+64 ints)
#define ATTN_FLOATS (64*132 + 128*68 + 64*68 + 64*132 + 64*132 + 192)
#define ATTN_SMEM   (ATTN_FLOATS*4 + 64*4)

__global__ __launch_bounds__(256) void attn_kernel(
    const float* __restrict__ Q, const float* __restrict__ K,
    const float* __restrict__ Vt, const int* __restrict__ amask,
    float* __restrict__ ctx)
{
    extern __shared__ float sm[];
    float* Qs  = sm;                       // [64][132]
    float* KV  = Qs + 64*LQD;              // K view [64][132] / V view [128][68]
    float* Ss  = KV + 128*LVD;             // [64][68]
    float* PVs = Ss + 64*LVD;              // [64][132]
    float* Os  = PVs + 64*LQD;             // [64][132]
    float* mrow = Os + 64*LQD;             // [64]
    float* lrow = mrow + 64;               // [64]
    float* arow = lrow + 64;               // [64]
    int*   msk  = (int*)(arow + 64);       // [64]

    const int tid = threadIdx.x;
    const int warp = tid >> 5;
    const int wm = warp >> 1;              // 0..3
    const int wn = warp & 1;               // 0..1
    const int b = blockIdx.y >> 5, h = blockIdx.y & 31;
    const int lt = blockIdx.x;

    // load Q tile (rounded to tf32)
    const float* Qb = Q + ((size_t)(b*Lq + lt*BQt)) * Hh + h*HDd;
    #pragma unroll
    for (int e = tid; e < 64*32; e += 256) {
        int r = e >> 5, c4 = e & 31;
        float4 v = *(const float4*)(Qb + (size_t)r * Hh + c4*4);
        v.x = tf32r(v.x); v.y = tf32r(v.y); v.z = tf32r(v.z); v.w = tf32r(v.w);
        *(float4*)(Qs + r*LQD + c4*4) = v;
    }
    for (int e = tid; e < 64*LQD; e += 256) Os[e] = 0.0f;
    if (tid < 64) { mrow[tid] = -1e30f; lrow[tid] = 0.0f; }
    __syncthreads();

    #pragma unroll 1
    for (int jt = 0; jt < Vn / BVt; jt++) {
        // ---- load K tile [v][d] ----
        const float* Kb = K + ((size_t)(b*Vn + jt*BVt)) * Hh + h*HDd;
        #pragma unroll
        for (int e = tid; e < 64*32; e += 256) {
            int r = e >> 5, c4 = e & 31;
            float4 v = *(const float4*)(Kb + (size_t)r * Hh + c4*4);
            v.x = tf32r(v.x); v.y = tf32r(v.y); v.z = tf32r(v.z); v.w = tf32r(v.w);
            *(float4*)(KV + r*LQD + c4*4) = v;
        }
        if (tid < 64) msk[tid] = amask[b*Vn + jt*BVt + tid];
        __syncthreads();

        // ---- S = Q K^T (64x64), warp tile 16x32 ----
        CFrag sacc[2];
        wmma::fill_fragment(sacc[0], 0.0f);
        wmma::fill_fragment(sacc[1], 0.0f);
        #pragma unroll
        for (int kk = 0; kk < HDd; kk += 8) {
            AFrag qa;
            wmma::load_matrix_sync(qa, Qs + (wm*16)*LQD + kk, LQD);
            #pragma unroll
            for (int j = 0; j < 2; j++) {
                BFrag kb;
                wmma::load_matrix_sync(kb, KV + (wn*32 + j*16)*LQD + kk, LQD);
                wmma::mma_sync(sacc[j], qa, kb, sacc[j]);
            }
        }
        #pragma unroll
        for (int j = 0; j < 2; j++)
            wmma::store_matrix_sync(Ss + (wm*16)*LVD + wn*32 + j*16, sacc[j], LVD, wmma::mem_row_major);
        __syncthreads();

        // ---- online softmax: 4 threads per row, 16 cols each ----
        {
            const int row = tid >> 2, q = tid & 3;
            float vals[16];
            float mloc = -1e30f;
            #pragma unroll
            for (int c0 = 0; c0 < 16; c0++) {
                int c = q*16 + c0;
                float s = msk[c] ? Ss[row*LVD + c] : -1e30f;
                vals[c0] = s;
                mloc = fmaxf(mloc, s);
            }
            mloc = fmaxf(mloc, __shfl_xor_sync(0xffffffffu, mloc, 1));
            mloc = fmaxf(mloc, __shfl_xor_sync(0xffffffffu, mloc, 2));
            float mold = mrow[row];
            float mnew = fmaxf(mold, mloc);
            float ssum = 0.0f;
            #pragma unroll
            for (int c0 = 0; c0 < 16; c0++) {
                float p = __expf(vals[c0] - mnew);
                ssum += p;
                Ss[row*LVD + q*16 + c0] = tf32r(p);
            }
            ssum += __shfl_xor_sync(0xffffffffu, ssum, 1);
            ssum += __shfl_xor_sync(0xffffffffu, ssum, 2);
            if (q == 0) {
                float al = __expf(mold - mnew);
                arow[row] = al;
                lrow[row] = lrow[row] * al + ssum;
                mrow[row] = mnew;
            }
        }
        __syncthreads();

        // ---- load V tile as [d][v] (reuses KV buffer) ----
        const float* Vb = Vt + ((size_t)(b*NHh + h) * HDd) * Vn + jt*BVt;
        #pragma unroll
        for (int e = tid; e < 128*16; e += 256) {
            int d = e >> 4, c4 = e & 15;
            float4 v = *(const float4*)(Vb + (size_t)d * Vn + c4*4);
            v.x = tf32r(v.x); v.y = tf32r(v.y); v.z = tf32r(v.z); v.w = tf32r(v.w);
            *(float4*)(KV + d*LVD + c4*4) = v;
        }
        __syncthreads();

        // ---- PV = P @ V (64x128), warp tile 16x64 ----
        CFrag pv[4];
        #pragma unroll
        for (int j = 0; j < 4; j++) wmma::fill_fragment(pv[j], 0.0f);
        #pragma unroll
        for (int kk = 0; kk < BVt; kk += 8) {
            AFrag pa;
            wmma::load_matrix_sync(pa, Ss + (wm*16)*LVD + kk, LVD);
            #pragma unroll
            for (int j = 0; j < 4; j++) {
                BFrag vb_;
                wmma::load_matrix_sync(vb_, KV + (wn*64 + j*16)*LVD + kk, LVD);
                wmma::mma_sync(pv[j], pa, vb_, pv[j]);
            }
        }
        #pragma unroll
        for (int j = 0; j < 4; j++)
            wmma::store_matrix_sync(PVs + (wm*16)*LQD + wn*64 + j*16, pv[j], LQD, wmma::mem_row_major);
        __syncthreads();

        // ---- O = O*alpha + PV ----
        #pragma unroll
        for (int e = tid; e < 64*32; e += 256) {
            int r = e >> 5, c4 = e & 31;
            float al = arow[r];
            float4 o = *(float4*)(Os + r*LQD + c4*4);
            float4 p = *(float4*)(PVs + r*LQD + c4*4);
            o.x = o.x*al + p.x; o.y = o.y*al + p.y;
            o.z = o.z*al + p.z; o.w = o.w*al + p.w;
            *(float4*)(Os + r*LQD + c4*4) = o;
        }
        __syncthreads();
    }

    // ---- final: ctx = O / l ----
    float* Cb = ctx + ((size_t)(b*Lq + lt*BQt)) * Hh + h*HDd;
    #pragma unroll
    for (int e = tid; e < 64*32; e += 256) {
        int r = e >> 5, c4 = e & 31;
        float inv = 1.0f / lrow[r];
        float4 o = *(float4*)(Os + r*LQD + c4*4);
        o.x *= inv; o.y *= inv; o.z *= inv; o.w *= inv;
        *(float4*)(Cb + (size_t)r * Hh + c4*4) = o;
    }
}

// ============================================================================
// LayerNorm over last dim (4096) per row
// ============================================================================
__global__ __launch_bounds__(256) void ln_kernel(
    const float* __restrict__ X, const float* __restrict__ g,
    const float* __restrict__ be, float* __restrict__ out)
{
    __shared__ float red[20];
    const int row = blockIdx.x, tid = threadIdx.x;
    const float* x = X + (size_t)row * Hh;
    float s = 0.0f, s2 = 0.0f;
    for (int i = tid; i < Hh; i += 256) { float v = x[i]; s += v; s2 += v*v; }
    #pragma unroll
    for (int o = 16; o; o >>= 1) {
        s  += __shfl_xor_sync(0xffffffffu, s,  o);
        s2 += __shfl_xor_sync(0xffffffffu, s2, o);
    }
    if ((tid & 31) == 0) { red[tid >> 5] = s; red[8 + (tid >> 5)] = s2; }
    __syncthreads();
    if (tid < 32) {
        float a = (tid < 8) ? red[tid] : 0.0f;
        float c = (tid < 8) ? red[8 + tid] : 0.0f;
        #pragma unroll
        for (int o = 4; o; o >>= 1) {
            a += __shfl_xor_sync(0xffffffffu, a, o);
            c += __shfl_xor_sync(0xffffffffu, c, o);
        }
        if (tid == 0) { red[16] = a; red[17] = c; }
    }
    __syncthreads();
    const float mu  = red[16] * (1.0f / Hh);
    const float var = red[17] * (1.0f / Hh) - mu*mu;
    const float inv = rsqrtf(var + 1e-5f);
    for (int i = tid; i < Hh; i += 256)
        out[(size_t)row * Hh + i] = (x[i] - mu) * inv * g[i] + be[i];
}

// ============================================================================
// host launcher
// ============================================================================
extern "C" void kernel_launch(void* const* d_in, const int* in_sizes, int n_in,
                              void* d_out, int out_size)
{
    const float* hidden = (const float*)d_in[0];
    const float* vision = (const float*)d_in[1];
    const int*   amask  = (const int*)  d_in[2];
    const float* Wq = (const float*)d_in[3];
    const float* bq = (const float*)d_in[4];
    const float* Wk = (const float*)d_in[5];
    const float* bk = (const float*)d_in[6];
    const float* Wv = (const float*)d_in[7];
    const float* bv = (const float*)d_in[8];
    const float* Wo = (const float*)d_in[9];
    const float* bo = (const float*)d_in[10];
    const float* lng = (const float*)d_in[11];
    const float* lnb = (const float*)d_in[12];
    float* out = (float*)d_out;

    float *pQ, *pK, *pVt, *pCtx, *pX;
    cudaGetSymbolAddress((void**)&pQ,   g_Q);
    cudaGetSymbolAddress((void**)&pK,   g_K);
    cudaGetSymbolAddress((void**)&pVt,  g_Vt);
    cudaGetSymbolAddress((void**)&pCtx, g_ctx);
    cudaGetSymbolAddress((void**)&pX,   g_X);

    cudaFuncSetAttribute(gemm_tf32,  cudaFuncAttributeMaxDynamicSharedMemorySize, GEMM_SMEM);
    cudaFuncSetAttribute(attn_kernel, cudaFuncAttributeMaxDynamicSharedMemorySize, ATTN_SMEM);

    dim3 gb(Hh / BN, Mrows / BM);    // (32, 16)
    dim3 tb(256);

    // Q = (hidden @ Wq^T + bq) * 1/sqrt(HD)
    gemm_tf32<<<gb, tb, GEMM_SMEM>>>(hidden, Wq, bq, nullptr, pQ, QSCALE, 0);
    // K = vision @ Wk^T + bk
    gemm_tf32<<<gb, tb, GEMM_SMEM>>>(vision, Wk, bk, nullptr, pK, 1.0f, 0);
    // V = vision @ Wv^T + bv   (stored transposed as [b, h*HD+d, v])
    gemm_tf32<<<gb, tb, GEMM_SMEM>>>(vision, Wv, bv, nullptr, pVt, 1.0f, 1);
    // attention -> ctx
    attn_kernel<<<dim3(Lq / BQt, Bb * NHh), tb, ATTN_SMEM>>>(pQ, pK, pVt, amask, pCtx);
    // X = ctx @ Wo^T + bo + hidden
    gemm_tf32<<<gb, tb, GEMM_SMEM>>>(pCtx, Wo, bo, hidden, pX, 1.0f, 2);
    // out = LayerNorm(X)
    ln_kernel<<<Mrows, tb>>>(pX, lng, lnb, out);
}

// round 2
// speedup vs baseline: 2.7959x; 2.7959x over previous
#include <cuda_runtime.h>
#include <cuda_bf16.h>
#include <mma.h>
#include <math.h>

using namespace nvcuda;
typedef __nv_bfloat16 bf16;

// ---------------- problem constants ----------------
#define Bb   2
#define Lq   1024
#define Vn   1024
#define Hh   4096
#define NHh  32
#define HDd  128
#define Mrows (Bb*Lq)          // 2048
#define QSCALE 0.08838834764831845f   // 1/sqrt(128)

// ---------------- scratch (device globals) ----------------------------------
__device__ bf16  g_hb [(size_t)Mrows*Hh];    // hidden bf16
__device__ bf16  g_vb [(size_t)Mrows*Hh];    // vision bf16
__device__ bf16  g_Wqb[(size_t)Hh*Hh];
__device__ bf16  g_Wkb[(size_t)Hh*Hh];
__device__ bf16  g_Wvb[(size_t)Hh*Hh];
__device__ bf16  g_Wob[(size_t)Hh*Hh];
__device__ bf16  g_Qb [(size_t)Mrows*Hh];    // Q (pre-scaled) bf16
__device__ bf16  g_Kb [(size_t)Mrows*Hh];
__device__ bf16  g_Vb [(size_t)Mrows*Hh];    // V rows [B*V, H]
__device__ bf16  g_ctx[(size_t)Mrows*Hh];    // attention output bf16
__device__ float g_X  [(size_t)Mrows*Hh];    // pre-LN fp32

// ---------------- WMMA types (bf16 m16n16k16) --------------------------------
typedef wmma::fragment<wmma::matrix_a, 16, 16, 16, bf16, wmma::row_major> AFrag;
typedef wmma::fragment<wmma::matrix_b, 16, 16, 16, bf16, wmma::col_major> BFragC; // B stored [n][k]
typedef wmma::fragment<wmma::matrix_b, 16, 16, 16, bf16, wmma::row_major> BFragR; // B stored [k][n]
typedef wmma::fragment<wmma::accumulator, 16, 16, 16, float>              CFrag;

// ---------------- cp.async helpers ------------------------------------------
__device__ __forceinline__ void cpasync16(void* sdst, const void* gsrc) {
    unsigned s = (unsigned)__cvta_generic_to_shared(sdst);
    asm volatile("cp.async.cg.shared.global [%0], [%1], 16;" :: "r"(s), "l"(gsrc));
}
__device__ __forceinline__ void cp_commit() { asm volatile("cp.async.commit_group;"); }
__device__ __forceinline__ void cp_wait1()  { asm volatile("cp.async.wait_group 1;"); }
__device__ __forceinline__ void cp_wait0()  { asm volatile("cp.async.wait_group 0;"); }

// ============================================================================
// fp32 -> bf16 conversion (vectorized)
// ============================================================================
__global__ __launch_bounds__(256) void f2bf(const float* __restrict__ in,
                                            bf16* __restrict__ out, int n4)
{
    int i = blockIdx.x * 256 + threadIdx.x;
    if (i < n4) {
        float4 v = ((const float4*)in)[i];
        __nv_bfloat162 a = __floats2bfloat162_rn(v.x, v.y);
        __nv_bfloat162 b = __floats2bfloat162_rn(v.z, v.w);
        uint2 p;
        p.x = *(unsigned*)&a; p.y = *(unsigned*)&b;
        ((uint2*)out)[i] = p;
    }
}

// ============================================================================
// bf16 GEMM: out = (A[M,K] @ W[N,K]^T + bias) * scale (+resid)
// CTA tile 128x256, BK=32, cp.async double-buffered, 8 warps (2x4), warp 64x64
// mode 0: bf16 out ; mode 2: fp32 out + resid
// ============================================================================
#define BM 128
#define BN 256
#define GBK 32
#define LDA 48                      // GBK + 16 halves pad
#define STAGE_A (BM*LDA)            // halves
#define STAGE_B (BN*LDA)
#define GEMM_SMEM ((2*(STAGE_A+STAGE_B))*2)  // bytes = 73728

__global__ __launch_bounds__(256, 1) void gemm_bf16(
    const bf16* __restrict__ A, const bf16* __restrict__ W,
    const float* __restrict__ bias, const float* __restrict__ resid,
    void* __restrict__ outv, float scale, int mode)
{
    extern __shared__ bf16 smh[];
    bf16* As = smh;                         // 2 stages
    bf16* Bs = smh + 2*STAGE_A;

    const int tid  = threadIdx.x;
    const int warp = tid >> 5, lane = tid & 31;
    const int wm = warp >> 2;               // 0..1 -> 64 rows
    const int wn = warp & 3;                // 0..3 -> 64 cols
    const int bm = blockIdx.y, bn = blockIdx.x;

    const bf16* Ab = A + (size_t)(bm*BM) * Hh;
    const bf16* Wb = W + (size_t)(bn*BN) * Hh;

    CFrag acc[4][4];
    #pragma unroll
    for (int i = 0; i < 4; i++)
        #pragma unroll
        for (int j = 0; j < 4; j++) wmma::fill_fragment(acc[i][j], 0.0f);

    // stage issue: A 512 chunks (2/thread), B 1024 chunks (4/thread)
    auto issue = [&](int stage, int k0) {
        bf16* Ad = As + stage*STAGE_A;
        bf16* Bd = Bs + stage*STAGE_B;
        #pragma unroll
        for (int i = 0; i < 2; i++) {
            int cid = tid + i*256, row = cid >> 2, c = (cid & 3) * 8;
            cpasync16(Ad + row*LDA + c, Ab + (size_t)row*Hh + k0 + c);
        }
        #pragma unroll
        for (int i = 0; i < 4; i++) {
            int cid = tid + i*256, row = cid >> 2, c = (cid & 3) * 8;
            cpasync16(Bd + row*LDA + c, Wb + (size_t)row*Hh + k0 + c);
        }
        cp_commit();
    };

    issue(0, 0);

    const int nk = Hh / GBK;                // 128
    #pragma unroll 1
    for (int kt = 0; kt < nk; kt++) {
        const int cur = kt & 1;
        if (kt + 1 < nk) { issue(cur ^ 1, (kt + 1) * GBK); cp_wait1(); }
        else             { cp_wait0(); }
        __syncthreads();

        const bf16* Ac = As + cur*STAGE_A;
        const bf16* Bc = Bs + cur*STAGE_B;
        #pragma unroll
        for (int kk = 0; kk < GBK; kk += 16) {
            AFrag fa[4]; BFragC fb[4];
            #pragma unroll
            for (int i = 0; i < 4; i++)
                wmma::load_matrix_sync(fa[i], Ac + (wm*64 + i*16)*LDA + kk, LDA);
            #pragma unroll
            for (int j = 0; j < 4; j++)
                wmma::load_matrix_sync(fb[j], Bc + (wn*64 + j*16)*LDA + kk, LDA);
            #pragma unroll
            for (int i = 0; i < 4; i++)
                #pragma unroll
                for (int j = 0; j < 4; j++)
                    wmma::mma_sync(acc[i][j], fa[i], fb[j], acc[i][j]);
        }
        __syncthreads();
    }

    // ---- epilogue via smem staging (reuse tile buffers) ----
    float* st = (float*)smh;
    float* stw = st + warp * 16 * 24;
    bf16*  outb = (bf16*)outv;
    float* outf = (float*)outv;

    #pragma unroll
    for (int i = 0; i < 4; i++) {
        #pragma unroll
        for (int j = 0; j < 4; j++) {
            wmma::store_matrix_sync(stw, acc[i][j], 24, wmma::mem_row_major);
            __syncwarp();
            const int m0 = bm*BM + wm*64 + i*16;
            const int n0 = bn*BN + wn*64 + j*16;
            #pragma unroll
            for (int e = lane; e < 256; e += 32) {
                int r = e >> 4, c = e & 15;
                int m = m0 + r, n = n0 + c;
                float v = (stw[r*24 + c] + bias[n]) * scale;
                if (mode == 0) outb[(size_t)m*Hh + n] = __float2bfloat16(v);
                else           outf[(size_t)m*Hh + n] = v + resid[(size_t)m*Hh + n];
            }
            __syncwarp();
        }
    }
}

// ============================================================================
// Flash cross-attention, bf16 MMA, fp32 softmax/accum.
// CTA: one (b,h) x 64 query rows; 16 kv tiles of 64. 8 warps (4x2).
// ============================================================================
#define BQt 64
#define BVt 64
#define LDQ 136         // bf16 halves (128 + 8)
#define LDS_S 68        // fp32
#define LDP 72          // bf16
#define LDO 132         // fp32
// bytes: Qs/Ks/Vs 3*64*136*2 + Ss 64*68*4 + Ps 64*72*2 + Os 64*132*4 + tails
#define ATTN_SMEM (3*64*LDQ*2 + 64*LDS_S*4 + 64*LDP*2 + 64*LDO*4 + 64*4*3 + 64*4)

__global__ __launch_bounds__(256, 2) void attn_kernel(
    const bf16* __restrict__ Q, const bf16* __restrict__ K,
    const bf16* __restrict__ V, const int* __restrict__ amask,
    bf16* __restrict__ ctx)
{
    extern __shared__ char smraw[];
    bf16*  Qs = (bf16*)smraw;                    // [64][136]
    bf16*  Ks = Qs + 64*LDQ;                     // [64][136]
    bf16*  Vs = Ks + 64*LDQ;                     // [64][136]
    float* Ss = (float*)(Vs + 64*LDQ);           // [64][68]
    bf16*  Ps = (bf16*)(Ss + 64*LDS_S);          // [64][72]
    float* Os = (float*)(Ps + 64*LDP);           // [64][132]
    float* mrow = Os + 64*LDO;
    float* lrow = mrow + 64;
    float* arow = lrow + 64;
    int*   msk  = (int*)(arow + 64);

    const int tid = threadIdx.x;
    const int warp = tid >> 5;
    const int wm = warp >> 1;                    // 0..3 (16 q-rows)
    const int wn = warp & 1;                     // 0..1
    const int b = blockIdx.y >> 5, h = blockIdx.y & 31;
    const int lt = blockIdx.x;

    // load Q tile [64][128] bf16 (16B chunks)
    const bf16* Qb = Q + ((size_t)(b*Lq + lt*BQt)) * Hh + h*HDd;
    #pragma unroll
    for (int e = tid; e < 64*16; e += 256) {
        int r = e >> 4, c = (e & 15) * 8;
        *(uint4*)(Qs + r*LDQ + c) = *(const uint4*)(Qb + (size_t)r*Hh + c);
    }
    for (int e = tid; e < 64*LDO; e += 256) Os[e] = 0.0f;
    if (tid < 64) { mrow[tid] = -1e30f; lrow[tid] = 0.0f; }
    __syncthreads();

    #pragma unroll 1
    for (int jt = 0; jt < Vn / BVt; jt++) {
        // ---- load K tile [v][d] ----
        const bf16* Kb = K + ((size_t)(b*Vn + jt*BVt)) * Hh + h*HDd;
        #pragma unroll
        for (int e = tid; e < 64*16; e += 256) {
            int r = e >> 4, c = (e & 15) * 8;
            *(uint4*)(Ks + r*LDQ + c) = *(const uint4*)(Kb + (size_t)r*Hh + c);
        }
        if (tid < 64) msk[tid] = amask[b*Vn + jt*BVt + tid];
        __syncthreads();

        // ---- S = Q K^T (64x64), warp tile 16x32 ----
        {
            CFrag sacc[2];
            wmma::fill_fragment(sacc[0], 0.0f);
            wmma::fill_fragment(sacc[1], 0.0f);
            #pragma unroll
            for (int kk = 0; kk < HDd; kk += 16) {
                AFrag qa;
                wmma::load_matrix_sync(qa, Qs + (wm*16)*LDQ + kk, LDQ);
                #pragma unroll
                for (int j = 0; j < 2; j++) {
                    BFragC kb;
                    wmma::load_matrix_sync(kb, Ks + (wn*32 + j*16)*LDQ + kk, LDQ);
                    wmma::mma_sync(sacc[j], qa, kb, sacc[j]);
                }
            }
            #pragma unroll
            for (int j = 0; j < 2; j++)
                wmma::store_matrix_sync(Ss + (wm*16)*LDS_S + wn*32 + j*16, sacc[j],
                                        LDS_S, wmma::mem_row_major);
        }
        __syncthreads();

        // ---- load V tile [v][d] (independent buffer) + online softmax ----
        const bf16* Vb = V + ((size_t)(b*Vn + jt*BVt)) * Hh + h*HDd;
        #pragma unroll
        for (int e = tid; e < 64*16; e += 256) {
            int r = e >> 4, c = (e & 15) * 8;
            *(uint4*)(Vs + r*LDQ + c) = *(const uint4*)(Vb + (size_t)r*Hh + c);
        }
        {
            const int row = tid >> 2, q = tid & 3;
            float vals[16];
            float mloc = -1e30f;
            #pragma unroll
            for (int c0 = 0; c0 < 16; c0++) {
                int c = q*16 + c0;
                float s = msk[c] ? Ss[row*LDS_S + c] : -1e30f;
                vals[c0] = s;
                mloc = fmaxf(mloc, s);
            }
            mloc = fmaxf(mloc, __shfl_xor_sync(0xffffffffu, mloc, 1));
            mloc = fmaxf(mloc, __shfl_xor_sync(0xffffffffu, mloc, 2));
            float mold = mrow[row];
            float mnew = fmaxf(mold, mloc);
            float ssum = 0.0f;
            #pragma unroll
            for (int c0 = 0; c0 < 16; c0++) {
                float p = __expf(vals[c0] - mnew);
                ssum += p;
                Ps[row*LDP + q*16 + c0] = __float2bfloat16(p);
            }
            ssum += __shfl_xor_sync(0xffffffffu, ssum, 1);
            ssum += __shfl_xor_sync(0xffffffffu, ssum, 2);
            if (q == 0) {
                arow[row] = __expf(mold - mnew);
                lrow[row] = lrow[row] * __expf(mold - mnew) + ssum;
                mrow[row] = mnew;
            }
        }
        __syncthreads();

        // ---- rescale O by alpha ----
        #pragma unroll
        for (int e = tid; e < 64*32; e += 256) {
            int r = e >> 5, c4 = e & 31;
            float al = arow[r];
            float4 o = *(float4*)(Os + r*LDO + c4*4);
            o.x *= al; o.y *= al; o.z *= al; o.w *= al;
            *(float4*)(Os + r*LDO + c4*4) = o;
        }
        __syncthreads();

        // ---- O += P @ V (64x128), warp tile 16x64; accumulate into O tiles ----
        {
            CFrag pv[4];
            #pragma unroll
            for (int j = 0; j < 4; j++)
                wmma::load_matrix_sync(pv[j], Os + (wm*16)*LDO + wn*64 + j*16,
                                       LDO, wmma::mem_row_major);
            #pragma unroll
            for (int kk = 0; kk < BVt; kk += 16) {
                AFrag pa;
                wmma::load_matrix_sync(pa, Ps + (wm*16)*LDP + kk, LDP);
                #pragma unroll
                for (int j = 0; j < 4; j++) {
                    BFragR vb_;
                    wmma::load_matrix_sync(vb_, Vs + kk*LDQ + wn*64 + j*16, LDQ);
                    wmma::mma_sync(pv[j], pa, vb_, pv[j]);
                }
            }
            #pragma unroll
            for (int j = 0; j < 4; j++)
                wmma::store_matrix_sync(Os + (wm*16)*LDO + wn*64 + j*16, pv[j],
                                        LDO, wmma::mem_row_major);
        }
        __syncthreads();
    }

    // ---- final: ctx = bf16(O / l) ----
    bf16* Cb = ctx + ((size_t)(b*Lq + lt*BQt)) * Hh + h*HDd;
    #pragma unroll
    for (int e = tid; e < 64*16; e += 256) {
        int r = e >> 4, c = (e & 15) * 8;
        float inv = 1.0f / lrow[r];
        bf16 tmp[8];
        #pragma unroll
        for (int u = 0; u < 8; u++)
            tmp[u] = __float2bfloat16(Os[r*LDO + c + u] * inv);
        *(uint4*)(Cb + (size_t)r*Hh + c) = *(uint4*)tmp;
    }
}

// ============================================================================
// LayerNorm over last dim (4096) per row
// ============================================================================
__global__ __launch_bounds__(256) void ln_kernel(
    const float* __restrict__ X, const float* __restrict__ g,
    const float* __restrict__ be, float* __restrict__ out)
{
    __shared__ float red[20];
    const int row = blockIdx.x, tid = threadIdx.x;
    const float* x = X + (size_t)row * Hh;
    float s = 0.0f, s2 = 0.0f;
    for (int i = tid; i < Hh; i += 256) { float v = x[i]; s += v; s2 += v*v; }
    #pragma unroll
    for (int o = 16; o; o >>= 1) {
        s  += __shfl_xor_sync(0xffffffffu, s,  o);
        s2 += __shfl_xor_sync(0xffffffffu, s2, o);
    }
    if ((tid & 31) == 0) { red[tid >> 5] = s; red[8 + (tid >> 5)] = s2; }
    __syncthreads();
    if (tid < 32) {
        float a = (tid < 8) ? red[tid] : 0.0f;
        float c = (tid < 8) ? red[8 + tid] : 0.0f;
        #pragma unroll
        for (int o = 4; o; o >>= 1) {
            a += __shfl_xor_sync(0xffffffffu, a, o);
            c += __shfl_xor_sync(0xffffffffu, c, o);
        }
        if (tid == 0) { red[16] = a; red[17] = c; }
    }
    __syncthreads();
    const float mu  = red[16] * (1.0f / Hh);
    const float var = red[17] * (1.0f / Hh) - mu*mu;
    const float inv = rsqrtf(var + 1e-5f);
    for (int i = tid; i < Hh; i += 256)
        out[(size_t)row * Hh + i] = (x[i] - mu) * inv * g[i] + be[i];
}

// ============================================================================
// host launcher
// ============================================================================
extern "C" void kernel_launch(void* const* d_in, const int* in_sizes, int n_in,
                              void* d_out, int out_size)
{
    const float* hidden = (const float*)d_in[0];
    const float* vision = (const float*)d_in[1];
    const int*   amask  = (const int*)  d_in[2];
    const float* Wq = (const float*)d_in[3];
    const float* bq = (const float*)d_in[4];
    const float* Wk = (const float*)d_in[5];
    const float* bk = (const float*)d_in[6];
    const float* Wv = (const float*)d_in[7];
    const float* bv = (const float*)d_in[8];
    const float* Wo = (const float*)d_in[9];
    const float* bo = (const float*)d_in[10];
    const float* lng = (const float*)d_in[11];
    const float* lnb = (const float*)d_in[12];
    float* out = (float*)d_out;

    bf16 *phb, *pvb, *pWq, *pWk, *pWv, *pWo, *pQ, *pK, *pV, *pCtx;
    float *pX;
    cudaGetSymbolAddress((void**)&phb, g_hb);
    cudaGetSymbolAddress((void**)&pvb, g_vb);
    cudaGetSymbolAddress((void**)&pWq, g_Wqb);
    cudaGetSymbolAddress((void**)&pWk, g_Wkb);
    cudaGetSymbolAddress((void**)&pWv, g_Wvb);
    cudaGetSymbolAddress((void**)&pWo, g_Wob);
    cudaGetSymbolAddress((void**)&pQ,  g_Qb);
    cudaGetSymbolAddress((void**)&pK,  g_Kb);
    cudaGetSymbolAddress((void**)&pV,  g_Vb);
    cudaGetSymbolAddress((void**)&pCtx, g_ctx);
    cudaGetSymbolAddress((void**)&pX,  g_X);

    cudaFuncSetAttribute(gemm_bf16,  cudaFuncAttributeMaxDynamicSharedMemorySize, GEMM_SMEM);
    cudaFuncSetAttribute(attn_kernel, cudaFuncAttributeMaxDynamicSharedMemorySize, ATTN_SMEM);

    const int actN4 = Mrows*Hh/4;        // 2,097,152
    const int wN4   = Hh*Hh/4;           // 4,194,304
    f2bf<<<(actN4+255)/256, 256>>>(hidden, phb, actN4);
    f2bf<<<(actN4+255)/256, 256>>>(vision, pvb, actN4);
    f2bf<<<(wN4+255)/256, 256>>>(Wq, pWq, wN4);
    f2bf<<<(wN4+255)/256, 256>>>(Wk, pWk, wN4);
    f2bf<<<(wN4+255)/256, 256>>>(Wv, pWv, wN4);
    f2bf<<<(wN4+255)/256, 256>>>(Wo, pWo, wN4);

    dim3 gb(Hh / BN, Mrows / BM);        // (16, 16)
    dim3 tb(256);

    gemm_bf16<<<gb, tb, GEMM_SMEM>>>(phb, pWq, bq, nullptr, pQ, QSCALE, 0);
    gemm_bf16<<<gb, tb, GEMM_SMEM>>>(pvb, pWk, bk, nullptr, pK, 1.0f, 0);
    gemm_bf16<<<gb, tb, GEMM_SMEM>>>(pvb, pWv, bv, nullptr, pV, 1.0f, 0);
    attn_kernel<<<dim3(Lq / BQt, Bb * NHh), tb, ATTN_SMEM>>>(pQ, pK, pV, amask, pCtx);
    gemm_bf16<<<gb, tb, GEMM_SMEM>>>(pCtx, pWo, bo, hidden, pX, 1.0f, 2);
    ln_kernel<<<Mrows, tb>>>(pX, lng, lnb, out);
}

// round 5
// speedup vs baseline: 3.3721x; 1.2061x over previous
#include <cuda_runtime.h>
#include <cuda_bf16.h>
#include <mma.h>
#include <math.h>
#include <cstdint>

using namespace nvcuda;
typedef __nv_bfloat16 bf16;

// ---------------- problem constants ----------------
#define Bb   2
#define Lq   1024
#define Vn   1024
#define Hh   4096
#define NHh  32
#define HDd  128
#define Mrows (Bb*Lq)          // 2048
#define QSCALE 0.08838834764831845f   // 1/sqrt(128)

// ---------------- scratch (device globals) ----------------------------------
__device__ bf16  g_hb [(size_t)Mrows*Hh];
__device__ bf16  g_vb [(size_t)Mrows*Hh];
__device__ bf16  g_Wqb[(size_t)Hh*Hh];
__device__ bf16  g_Wkb[(size_t)Hh*Hh];
__device__ bf16  g_Wvb[(size_t)Hh*Hh];
__device__ bf16  g_Wob[(size_t)Hh*Hh];
__device__ bf16  g_Qb [(size_t)Mrows*Hh];
__device__ bf16  g_Kb [(size_t)Mrows*Hh];
__device__ bf16  g_Vb [(size_t)Mrows*Hh];
__device__ bf16  g_ctx[(size_t)Mrows*Hh];
__device__ float g_X  [(size_t)Mrows*Hh];

// ---------------- low-level helpers -----------------------------------------
__device__ __forceinline__ void cpasync16(void* sdst, const void* gsrc) {
    unsigned s = (unsigned)__cvta_generic_to_shared(sdst);
    asm volatile("cp.async.cg.shared.global [%0], [%1], 16;" :: "r"(s), "l"(gsrc));
}
__device__ __forceinline__ void cp_commit() { asm volatile("cp.async.commit_group;"); }
__device__ __forceinline__ void cp_wait2()  { asm volatile("cp.async.wait_group 2;"); }
__device__ __forceinline__ void cp_wait1()  { asm volatile("cp.async.wait_group 1;"); }
__device__ __forceinline__ void cp_wait0()  { asm volatile("cp.async.wait_group 0;"); }

__device__ __forceinline__ void ldsm4(uint32_t& r0, uint32_t& r1, uint32_t& r2, uint32_t& r3,
                                      const void* p) {
    unsigned a = (unsigned)__cvta_generic_to_shared(p);
    asm volatile("ldmatrix.sync.aligned.m8n8.x4.shared.b16 {%0,%1,%2,%3}, [%4];"
                 : "=r"(r0), "=r"(r1), "=r"(r2), "=r"(r3) : "r"(a));
}

__device__ __forceinline__ void mma16816(float* c, const uint32_t* a, const uint32_t* b) {
    asm volatile(
        "mma.sync.aligned.m16n8k16.row.col.f32.bf16.bf16.f32 "
        "{%0,%1,%2,%3}, {%4,%5,%6,%7}, {%8,%9}, {%0,%1,%2,%3};"
        : "+f"(c[0]), "+f"(c[1]), "+f"(c[2]), "+f"(c[3])
        : "r"(a[0]), "r"(a[1]), "r"(a[2]), "r"(a[3]), "r"(b[0]), "r"(b[1]));
}

// ============================================================================
// fused fp32 -> bf16 conversion for all 6 tensors
// ============================================================================
#define A4 ((size_t)Mrows*Hh/4)   // 2M float4
#define W4 ((size_t)Hh*Hh/4)      // 4M float4
#define CONV_TOTAL (2*A4 + 4*W4)  // 20M float4

__global__ __launch_bounds__(256) void f2bf_all(
    const float* __restrict__ h, const float* __restrict__ v,
    const float* __restrict__ wq, const float* __restrict__ wk,
    const float* __restrict__ wv, const float* __restrict__ wo,
    bf16* __restrict__ dh, bf16* __restrict__ dv,
    bf16* __restrict__ dwq, bf16* __restrict__ dwk,
    bf16* __restrict__ dwv, bf16* __restrict__ dwo)
{
    size_t i = (size_t)blockIdx.x * 256 + threadIdx.x;
    if (i >= CONV_TOTAL) return;
    const float* src; bf16* dst; size_t off;
    if (i < A4)            { src = h;  dst = dh;  off = i; }
    else if (i < 2*A4)     { src = v;  dst = dv;  off = i - A4; }
    else {
        size_t j = i - 2*A4;
        int w = (int)(j >> 22);          // W4 = 1<<22
        off = j & (W4 - 1);
        src = (w == 0) ? wq : (w == 1) ? wk : (w == 2) ? wv : wo;
        dst = (w == 0) ? dwq : (w == 1) ? dwk : (w == 2) ? dwv : dwo;
    }
    float4 x = ((const float4*)src)[off];
    __nv_bfloat162 a = __floats2bfloat162_rn(x.x, x.y);
    __nv_bfloat162 b = __floats2bfloat162_rn(x.z, x.w);
    uint2 p; p.x = *(unsigned*)&a; p.y = *(unsigned*)&b;
    ((uint2*)dst)[off] = p;
}

// ============================================================================
// mma.sync bf16 GEMM: out = (A[M,K] @ W[N,K]^T + bias) * scale (+resid)
// CTA tile 128x256, BK=32, 3-stage cp.async, 8 warps (2x4), warp tile 64x64.
// smem rows padded to 40 halves (80B stride) -> conflict-free ldmatrix.
// mode 0: bf16 out ; mode 2: fp32 out + resid
// ============================================================================
#define TBM 128
#define TBN 256
#define TKC 32
#define NST 3
#define LDT 40                                  // halves per smem row
#define STG_HALVES ((TBM+TBN)*LDT)              // 15360
#define GEMM_SMEM (NST*STG_HALVES*2)            // 92160 bytes
#define NKI (Hh / TKC)                          // 128

__device__ __forceinline__ void load_stage(bf16* smb, const bf16* Ab, const bf16* Wb,
                                           int slot, int k0, int tid)
{
    bf16* Sa = smb + (size_t)slot * STG_HALVES;
    bf16* Sb = Sa + TBM * LDT;
    #pragma unroll
    for (int i = 0; i < 2; i++) {               // A: 512 chunks
        int ch = tid + i * 256, r = ch >> 2, c = ch & 3;
        cpasync16(Sa + r * LDT + c * 8, Ab + (size_t)r * Hh + k0 + c * 8);
    }
    #pragma unroll
    for (int i = 0; i < 4; i++) {               // B: 1024 chunks
        int ch = tid + i * 256, r = ch >> 2, c = ch & 3;
        cpasync16(Sb + r * LDT + c * 8, Wb + (size_t)r * Hh + k0 + c * 8);
    }
    cp_commit();
}

__global__ __launch_bounds__(256, 1) void gemm_mma(
    const bf16* __restrict__ A, const bf16* __restrict__ W,
    const float* __restrict__ bias, const float* __restrict__ resid,
    void* __restrict__ outv, float scale, int mode)
{
    extern __shared__ bf16 smb[];
    const int tid = threadIdx.x, warp = tid >> 5, lane = tid & 31;
    const int wm = warp >> 2;                   // 0..1  -> 64 rows
    const int wn = warp & 3;                    // 0..3  -> 64 cols
    const int bn = blockIdx.x, bm = blockIdx.y;

    const bf16* Ab = A + (size_t)(bm * TBM) * Hh;
    const bf16* Wb = W + (size_t)(bn * TBN) * Hh;

    float acc[4][8][4];
    #pragma unroll
    for (int i = 0; i < 4; i++)
        #pragma unroll
        for (int j = 0; j < 8; j++)
            #pragma unroll
            for (int e = 0; e < 4; e++) acc[i][j][e] = 0.0f;

    load_stage(smb, Ab, Wb, 0, 0, tid);
    load_stage(smb, Ab, Wb, 1, TKC, tid);

    // per-lane ldmatrix source offsets (element units, within a stage)
    const int a_row = (lane & 15);              // + i*16 + wm*64
    const int a_kof = (lane >> 4) * 8;          // + ks
    const int b_row = (lane & 7) + ((lane >> 4) * 8);   // n-row within 16-group
    const int b_kof = ((lane >> 3) & 1) * 8;    // + ks

    #pragma unroll 1
    for (int kt = 0; kt < NKI; kt++) {
        const int slot = kt % NST;
        if (kt + 2 < NKI) {
            load_stage(smb, Ab, Wb, (kt + 2) % NST, (kt + 2) * TKC, tid);
            cp_wait2();
        } else if (kt + 1 < NKI) cp_wait1();
        else                     cp_wait0();
        __syncthreads();

        const bf16* Sa = smb + (size_t)slot * STG_HALVES;
        const bf16* Sb = Sa + TBM * LDT;

        #pragma unroll
        for (int ks = 0; ks < TKC; ks += 16) {
            uint32_t af[4][4];
            #pragma unroll
            for (int i = 0; i < 4; i++)
                ldsm4(af[i][0], af[i][1], af[i][2], af[i][3],
                      Sa + (wm*64 + i*16 + a_row) * LDT + ks + a_kof);
            uint32_t bfr[8][2];
            #pragma unroll
            for (int j = 0; j < 4; j++) {
                uint32_t r0, r1, r2, r3;
                ldsm4(r0, r1, r2, r3,
                      Sb + (wn*64 + j*16 + b_row) * LDT + ks + b_kof);
                bfr[j*2  ][0] = r0; bfr[j*2  ][1] = r1;
                bfr[j*2+1][0] = r2; bfr[j*2+1][1] = r3;
            }
            #pragma unroll
            for (int i = 0; i < 4; i++)
                #pragma unroll
                for (int j = 0; j < 8; j++)
                    mma16816(acc[i][j], af[i], bfr[j]);
        }
        __syncthreads();
    }

    // ---- register epilogue ----
    bf16*  outb = (bf16*)outv;
    float* outf = (float*)outv;
    const int mbase = bm * TBM + wm * 64 + (lane >> 2);
    const int nbase = bn * TBN + wn * 64 + (lane & 3) * 2;
    #pragma unroll
    for (int i = 0; i < 4; i++) {
        #pragma unroll
        for (int j = 0; j < 8; j++) {
            const int n = nbase + j * 8;
            const float b0 = bias[n], b1 = bias[n + 1];
            #pragma unroll
            for (int half = 0; half < 2; half++) {
                const int m = mbase + i * 16 + half * 8;
                float v0 = (acc[i][j][half*2]     + b0) * scale;
                float v1 = (acc[i][j][half*2 + 1] + b1) * scale;
                if (mode == 0) {
                    __nv_bfloat162 p = __floats2bfloat162_rn(v0, v1);
                    *(__nv_bfloat162*)(outb + (size_t)m * Hh + n) = p;
                } else {
                    const float* rp = resid + (size_t)m * Hh + n;
                    float2 o; o.x = v0 + rp[0]; o.y = v1 + rp[1];
                    *(float2*)(outf + (size_t)m * Hh + n) = o;
                }
            }
        }
    }
}

// ============================================================================
// Flash cross-attention (WMMA bf16) — unchanged from round 2
// ============================================================================
typedef wmma::fragment<wmma::matrix_a, 16, 16, 16, bf16, wmma::row_major> AFrag;
typedef wmma::fragment<wmma::matrix_b, 16, 16, 16, bf16, wmma::col_major> BFragC;
typedef wmma::fragment<wmma::matrix_b, 16, 16, 16, bf16, wmma::row_major> BFragR;
typedef wmma::fragment<wmma::accumulator, 16, 16, 16, float>              CFrag;

#define BQt 64
#define BVt 64
#define LDQ 136
#define LDS_S 68
#define LDP 72
#define LDO 132
#define ATTN_SMEM (3*64*LDQ*2 + 64*LDS_S*4 + 64*LDP*2 + 64*LDO*4 + 64*4*3 + 64*4)

__global__ __launch_bounds__(256, 2) void attn_kernel(
    const bf16* __restrict__ Q, const bf16* __restrict__ K,
    const bf16* __restrict__ V, const int* __restrict__ amask,
    bf16* __restrict__ ctx)
{
    extern __shared__ char smraw[];
    bf16*  Qs = (bf16*)smraw;
    bf16*  Ks = Qs + 64*LDQ;
    bf16*  Vs = Ks + 64*LDQ;
    float* Ss = (float*)(Vs + 64*LDQ);
    bf16*  Ps = (bf16*)(Ss + 64*LDS_S);
    float* Os = (float*)(Ps + 64*LDP);
    float* mrow = Os + 64*LDO;
    float* lrow = mrow + 64;
    float* arow = lrow + 64;
    int*   msk  = (int*)(arow + 64);

    const int tid = threadIdx.x;
    const int warp = tid >> 5;
    const int wm = warp >> 1;
    const int wn = warp & 1;
    const int b = blockIdx.y >> 5, h = blockIdx.y & 31;
    const int lt = blockIdx.x;

    const bf16* Qb = Q + ((size_t)(b*Lq + lt*BQt)) * Hh + h*HDd;
    #pragma unroll
    for (int e = tid; e < 64*16; e += 256) {
        int r = e >> 4, c = (e & 15) * 8;
        *(uint4*)(Qs + r*LDQ + c) = *(const uint4*)(Qb + (size_t)r*Hh + c);
    }
    for (int e = tid; e < 64*LDO; e += 256) Os[e] = 0.0f;
    if (tid < 64) { mrow[tid] = -1e30f; lrow[tid] = 0.0f; }
    __syncthreads();

    #pragma unroll 1
    for (int jt = 0; jt < Vn / BVt; jt++) {
        const bf16* Kb = K + ((size_t)(b*Vn + jt*BVt)) * Hh + h*HDd;
        #pragma unroll
        for (int e = tid; e < 64*16; e += 256) {
            int r = e >> 4, c = (e & 15) * 8;
            *(uint4*)(Ks + r*LDQ + c) = *(const uint4*)(Kb + (size_t)r*Hh + c);
        }
        if (tid < 64) msk[tid] = amask[b*Vn + jt*BVt + tid];
        __syncthreads();

        {
            CFrag sacc[2];
            wmma::fill_fragment(sacc[0], 0.0f);
            wmma::fill_fragment(sacc[1], 0.0f);
            #pragma unroll
            for (int kk = 0; kk < HDd; kk += 16) {
                AFrag qa;
                wmma::load_matrix_sync(qa, Qs + (wm*16)*LDQ + kk, LDQ);
                #pragma unroll
                for (int j = 0; j < 2; j++) {
                    BFragC kb;
                    wmma::load_matrix_sync(kb, Ks + (wn*32 + j*16)*LDQ + kk, LDQ);
                    wmma::mma_sync(sacc[j], qa, kb, sacc[j]);
                }
            }
            #pragma unroll
            for (int j = 0; j < 2; j++)
                wmma::store_matrix_sync(Ss + (wm*16)*LDS_S + wn*32 + j*16, sacc[j],
                                        LDS_S, wmma::mem_row_major);
        }
        __syncthreads();

        const bf16* Vb = V + ((size_t)(b*Vn + jt*BVt)) * Hh + h*HDd;
        #pragma unroll
        for (int e = tid; e < 64*16; e += 256) {
            int r = e >> 4, c = (e & 15) * 8;
            *(uint4*)(Vs + r*LDQ + c) = *(const uint4*)(Vb + (size_t)r*Hh + c);
        }
        {
            const int row = tid >> 2, q = tid & 3;
            float vals[16];
            float mloc = -1e30f;
            #pragma unroll
            for (int c0 = 0; c0 < 16; c0++) {
                int c = q*16 + c0;
                float s = msk[c] ? Ss[row*LDS_S + c] : -1e30f;
                vals[c0] = s;
                mloc = fmaxf(mloc, s);
            }
            mloc = fmaxf(mloc, __shfl_xor_sync(0xffffffffu, mloc, 1));
            mloc = fmaxf(mloc, __shfl_xor_sync(0xffffffffu, mloc, 2));
            float mold = mrow[row];
            float mnew = fmaxf(mold, mloc);
            float ssum = 0.0f;
            #pragma unroll
            for (int c0 = 0; c0 < 16; c0++) {
                float p = __expf(vals[c0] - mnew);
                ssum += p;
                Ps[row*LDP + q*16 + c0] = __float2bfloat16(p);
            }
            ssum += __shfl_xor_sync(0xffffffffu, ssum, 1);
            ssum += __shfl_xor_sync(0xffffffffu, ssum, 2);
            if (q == 0) {
                float al = __expf(mold - mnew);
                arow[row] = al;
                lrow[row] = lrow[row] * al + ssum;
                mrow[row] = mnew;
            }
        }
        __syncthreads();

        #pragma unroll
        for (int e = tid; e < 64*32; e += 256) {
            int r = e >> 5, c4 = e & 31;
            float al = arow[r];
            float4 o = *(float4*)(Os + r*LDO + c4*4);
            o.x *= al; o.y *= al; o.z *= al; o.w *= al;
            *(float4*)(Os + r*LDO + c4*4) = o;
        }
        __syncthreads();

        {
            CFrag pv[4];
            #pragma unroll
            for (int j = 0; j < 4; j++)
                wmma::load_matrix_sync(pv[j], Os + (wm*16)*LDO + wn*64 + j*16,
                                       LDO, wmma::mem_row_major);
            #pragma unroll
            for (int kk = 0; kk < BVt; kk += 16) {
                AFrag pa;
                wmma::load_matrix_sync(pa, Ps + (wm*16)*LDP + kk, LDP);
                #pragma unroll
                for (int j = 0; j < 4; j++) {
                    BFragR vb_;
                    wmma::load_matrix_sync(vb_, Vs + kk*LDQ + wn*64 + j*16, LDQ);
                    wmma::mma_sync(pv[j], pa, vb_, pv[j]);
                }
            }
            #pragma unroll
            for (int j = 0; j < 4; j++)
                wmma::store_matrix_sync(Os + (wm*16)*LDO + wn*64 + j*16, pv[j],
                                        LDO, wmma::mem_row_major);
        }
        __syncthreads();
    }

    bf16* Cb = ctx + ((size_t)(b*Lq + lt*BQt)) * Hh + h*HDd;
    #pragma unroll
    for (int e = tid; e < 64*16; e += 256) {
        int r = e >> 4, c = (e & 15) * 8;
        float inv = 1.0f / lrow[r];
        bf16 tmp[8];
        #pragma unroll
        for (int u = 0; u < 8; u++)
            tmp[u] = __float2bfloat16(Os[r*LDO + c + u] * inv);
        *(uint4*)(Cb + (size_t)r*Hh + c) = *(uint4*)tmp;
    }
}

// ============================================================================
// LayerNorm over last dim (4096) per row
// ============================================================================
__global__ __launch_bounds__(256) void ln_kernel(
    const float* __restrict__ X, const float* __restrict__ g,
    const float* __restrict__ be, float* __restrict__ out)
{
    __shared__ float red[20];
    const int row = blockIdx.x, tid = threadIdx.x;
    const float* x = X + (size_t)row * Hh;
    float s = 0.0f, s2 = 0.0f;
    for (int i = tid; i < Hh; i += 256) { float v = x[i]; s += v; s2 += v*v; }
    #pragma unroll
    for (int o = 16; o; o >>= 1) {
        s  += __shfl_xor_sync(0xffffffffu, s,  o);
        s2 += __shfl_xor_sync(0xffffffffu, s2, o);
    }
    if ((tid & 31) == 0) { red[tid >> 5] = s; red[8 + (tid >> 5)] = s2; }
    __syncthreads();
    if (tid < 32) {
        float a = (tid < 8) ? red[tid] : 0.0f;
        float c = (tid < 8) ? red[8 + tid] : 0.0f;
        #pragma unroll
        for (int o = 4; o; o >>= 1) {
            a += __shfl_xor_sync(0xffffffffu, a, o);
            c += __shfl_xor_sync(0xffffffffu, c, o);
        }
        if (tid == 0) { red[16] = a; red[17] = c; }
    }
    __syncthreads();
    const float mu  = red[16] * (1.0f / Hh);
    const float var = red[17] * (1.0f / Hh) - mu*mu;
    const float inv = rsqrtf(var + 1e-5f);
    for (int i = tid; i < Hh; i += 256)
        out[(size_t)row * Hh + i] = (x[i] - mu) * inv * g[i] + be[i];
}

// ============================================================================
// host launcher
// ============================================================================
extern "C" void kernel_launch(void* const* d_in, const int* in_sizes, int n_in,
                              void* d_out, int out_size)
{
    const float* hidden = (const float*)d_in[0];
    const float* vision = (const float*)d_in[1];
    const int*   amask  = (const int*)  d_in[2];
    const float* Wq = (const float*)d_in[3];
    const float* bq = (const float*)d_in[4];
    const float* Wk = (const float*)d_in[5];
    const float* bk = (const float*)d_in[6];
    const float* Wv = (const float*)d_in[7];
    const float* bv = (const float*)d_in[8];
    const float* Wo = (const float*)d_in[9];
    const float* bo = (const float*)d_in[10];
    const float* lng = (const float*)d_in[11];
    const float* lnb = (const float*)d_in[12];
    float* out = (float*)d_out;

    bf16 *phb, *pvb, *pWq, *pWk, *pWv, *pWo, *pQ, *pK, *pV, *pCtx;
    float *pX;
    cudaGetSymbolAddress((void**)&phb, g_hb);
    cudaGetSymbolAddress((void**)&pvb, g_vb);
    cudaGetSymbolAddress((void**)&pWq, g_Wqb);
    cudaGetSymbolAddress((void**)&pWk, g_Wkb);
    cudaGetSymbolAddress((void**)&pWv, g_Wvb);
    cudaGetSymbolAddress((void**)&pWo, g_Wob);
    cudaGetSymbolAddress((void**)&pQ,  g_Qb);
    cudaGetSymbolAddress((void**)&pK,  g_Kb);
    cudaGetSymbolAddress((void**)&pV,  g_Vb);
    cudaGetSymbolAddress((void**)&pCtx, g_ctx);
    cudaGetSymbolAddress((void**)&pX,  g_X);

    cudaFuncSetAttribute(gemm_mma,    cudaFuncAttributeMaxDynamicSharedMemorySize, GEMM_SMEM);
    cudaFuncSetAttribute(attn_kernel, cudaFuncAttributeMaxDynamicSharedMemorySize, ATTN_SMEM);

    const long long total4 = (long long)CONV_TOTAL;
    f2bf_all<<<(unsigned)((total4 + 255) / 256), 256>>>(
        hidden, vision, Wq, Wk, Wv, Wo, phb, pvb, pWq, pWk, pWv, pWo);

    dim3 gb(Hh / TBN, Mrows / TBM);      // (16, 16)
    dim3 tb(256);

    gemm_mma<<<gb, tb, GEMM_SMEM>>>(phb, pWq, bq, nullptr, pQ, QSCALE, 0);
    gemm_mma<<<gb, tb, GEMM_SMEM>>>(pvb, pWk, bk, nullptr, pK, 1.0f, 0);
    gemm_mma<<<gb, tb, GEMM_SMEM>>>(pvb, pWv, bv, nullptr, pV, 1.0f, 0);
    attn_kernel<<<dim3(Lq / BQt, Bb * NHh), tb, ATTN_SMEM>>>(pQ, pK, pV, amask, pCtx);
    gemm_mma<<<gb, tb, GEMM_SMEM>>>(pCtx, pWo, bo, hidden, pX, 1.0f, 2);
    ln_kernel<<<Mrows, tb>>>(pX, lng, lnb, out);
}

// round 6
// speedup vs baseline: 3.7658x; 1.1167x over previous
#include <cuda_runtime.h>
#include <cuda_bf16.h>
#include <mma.h>
#include <math.h>
#include <cstdint>

using namespace nvcuda;
typedef __nv_bfloat16 bf16;

// ---------------- problem constants ----------------
#define Bb   2
#define Lq   1024
#define Vn   1024
#define Hh   4096
#define NHh  32
#define HDd  128
#define Mrows (Bb*Lq)          // 2048
#define QSCALE 0.08838834764831845f   // 1/sqrt(128)

// ---------------- scratch (device globals) ----------------------------------
__device__ bf16  g_hb [(size_t)Mrows*Hh];
__device__ bf16  g_vb [(size_t)Mrows*Hh];
__device__ bf16  g_Wqb[(size_t)Hh*Hh];
__device__ bf16  g_Wkb[(size_t)Hh*Hh];
__device__ bf16  g_Wvb[(size_t)Hh*Hh];
__device__ bf16  g_Wob[(size_t)Hh*Hh];
__device__ bf16  g_Qb [(size_t)Mrows*Hh];
__device__ bf16  g_Kb [(size_t)Mrows*Hh];
__device__ bf16  g_Vb [(size_t)Mrows*Hh];
__device__ bf16  g_ctx[(size_t)Mrows*Hh];
__device__ float g_X  [(size_t)Mrows*Hh];

// ---------------- low-level helpers -----------------------------------------
__device__ __forceinline__ void cpasync16(void* sdst, const void* gsrc) {
    unsigned s = (unsigned)__cvta_generic_to_shared(sdst);
    asm volatile("cp.async.cg.shared.global [%0], [%1], 16;" :: "r"(s), "l"(gsrc));
}
__device__ __forceinline__ void cp_commit() { asm volatile("cp.async.commit_group;"); }
__device__ __forceinline__ void cp_wait2()  { asm volatile("cp.async.wait_group 2;"); }
__device__ __forceinline__ void cp_wait1()  { asm volatile("cp.async.wait_group 1;"); }
__device__ __forceinline__ void cp_wait0()  { asm volatile("cp.async.wait_group 0;"); }

__device__ __forceinline__ void ldsm4(uint32_t& r0, uint32_t& r1, uint32_t& r2, uint32_t& r3,
                                      const void* p) {
    unsigned a = (unsigned)__cvta_generic_to_shared(p);
    asm volatile("ldmatrix.sync.aligned.m8n8.x4.shared.b16 {%0,%1,%2,%3}, [%4];"
                 : "=r"(r0), "=r"(r1), "=r"(r2), "=r"(r3) : "r"(a));
}

__device__ __forceinline__ void mma16816(float* c, const uint32_t* a, const uint32_t* b) {
    asm volatile(
        "mma.sync.aligned.m16n8k16.row.col.f32.bf16.bf16.f32 "
        "{%0,%1,%2,%3}, {%4,%5,%6,%7}, {%8,%9}, {%0,%1,%2,%3};"
        : "+f"(c[0]), "+f"(c[1]), "+f"(c[2]), "+f"(c[3])
        : "r"(a[0]), "r"(a[1]), "r"(a[2]), "r"(a[3]), "r"(b[0]), "r"(b[1]));
}

// ============================================================================
// fused fp32 -> bf16 conversion for all 6 tensors
// ============================================================================
#define A4 ((size_t)Mrows*Hh/4)   // 2M float4
#define W4 ((size_t)Hh*Hh/4)      // 4M float4
#define CONV_TOTAL (2*A4 + 4*W4)  // 20M float4

__global__ __launch_bounds__(256) void f2bf_all(
    const float* __restrict__ h, const float* __restrict__ v,
    const float* __restrict__ wq, const float* __restrict__ wk,
    const float* __restrict__ wv, const float* __restrict__ wo,
    bf16* __restrict__ dh, bf16* __restrict__ dv,
    bf16* __restrict__ dwq, bf16* __restrict__ dwk,
    bf16* __restrict__ dwv, bf16* __restrict__ dwo)
{
    size_t i = (size_t)blockIdx.x * 256 + threadIdx.x;
    if (i >= CONV_TOTAL) return;
    const float* src; bf16* dst; size_t off;
    if (i < A4)            { src = h;  dst = dh;  off = i; }
    else if (i < 2*A4)     { src = v;  dst = dv;  off = i - A4; }
    else {
        size_t j = i - 2*A4;
        int w = (int)(j >> 22);          // W4 = 1<<22
        off = j & (W4 - 1);
        src = (w == 0) ? wq : (w == 1) ? wk : (w == 2) ? wv : wo;
        dst = (w == 0) ? dwq : (w == 1) ? dwk : (w == 2) ? dwv : dwo;
    }
    float4 x = ((const float4*)src)[off];
    __nv_bfloat162 a = __floats2bfloat162_rn(x.x, x.y);
    __nv_bfloat162 b = __floats2bfloat162_rn(x.z, x.w);
    uint2 p; p.x = *(unsigned*)&a; p.y = *(unsigned*)&b;
    ((uint2*)dst)[off] = p;
}

// ============================================================================
// mma.sync bf16 GEMM: out = (A[M,K] @ W[N,K]^T + bias) * scale (+resid)
// CTA tile 128x256, BK=64, 3-stage cp.async, 8 warps (2x4), warp tile 64x64.
// smem rows padded to 72 halves (144B stride) -> conflict-free ldmatrix.
// Fragment double-buffering: ldsm for k-step s+1 overlaps mma of step s.
// mode 0: bf16 out ; mode 2: fp32 out + resid
// ============================================================================
#define TBM 128
#define TBN 256
#define TKC 64
#define NST 3
#define LDT 72                                  // halves per smem row
#define STG_HALVES ((TBM+TBN)*LDT)              // 27648
#define GEMM_SMEM (NST*STG_HALVES*2)            // 165888 bytes
#define NKI (Hh / TKC)                          // 64

__device__ __forceinline__ void load_stage(bf16* smb, const bf16* Ab, const bf16* Wb,
                                           int slot, int k0, int tid)
{
    bf16* Sa = smb + (size_t)slot * STG_HALVES;
    bf16* Sb = Sa + TBM * LDT;
    #pragma unroll
    for (int i = 0; i < 4; i++) {               // A: 128 rows x 8 chunks = 1024
        int ch = tid + i * 256, r = ch >> 3, c = ch & 7;
        cpasync16(Sa + r * LDT + c * 8, Ab + (size_t)r * Hh + k0 + c * 8);
    }
    #pragma unroll
    for (int i = 0; i < 8; i++) {               // B: 256 rows x 8 chunks = 2048
        int ch = tid + i * 256, r = ch >> 3, c = ch & 7;
        cpasync16(Sb + r * LDT + c * 8, Wb + (size_t)r * Hh + k0 + c * 8);
    }
    cp_commit();
}

__global__ __launch_bounds__(256, 1) void gemm_mma(
    const bf16* __restrict__ A, const bf16* __restrict__ W,
    const float* __restrict__ bias, const float* __restrict__ resid,
    void* __restrict__ outv, float scale, int mode)
{
    extern __shared__ bf16 smb[];
    const int tid = threadIdx.x, warp = tid >> 5, lane = tid & 31;
    const int wm = warp >> 2;                   // 0..1  -> 64 rows
    const int wn = warp & 3;                    // 0..3  -> 64 cols
    const int bn = blockIdx.x, bm = blockIdx.y;

    const bf16* Ab = A + (size_t)(bm * TBM) * Hh;
    const bf16* Wb = W + (size_t)(bn * TBN) * Hh;

    float acc[4][8][4];
    #pragma unroll
    for (int i = 0; i < 4; i++)
        #pragma unroll
        for (int j = 0; j < 8; j++)
            #pragma unroll
            for (int e = 0; e < 4; e++) acc[i][j][e] = 0.0f;

    load_stage(smb, Ab, Wb, 0, 0, tid);
    load_stage(smb, Ab, Wb, 1, TKC, tid);

    // per-lane ldmatrix source offsets (element units, within a stage)
    const int a_row = (lane & 15);              // + i*16 + wm*64
    const int a_kof = (lane >> 4) * 8;          // + ks
    const int b_row = (lane & 7) + ((lane >> 4) * 8);   // n-row within 16-group
    const int b_kof = ((lane >> 3) & 1) * 8;    // + ks

    uint32_t af[2][4][4];
    uint32_t bfr[2][8][2];

    #pragma unroll 1
    for (int kt = 0; kt < NKI; kt++) {
        const int slot = kt % NST;
        if (kt + 2 < NKI) {
            load_stage(smb, Ab, Wb, (kt + 2) % NST, (kt + 2) * TKC, tid);
            cp_wait2();
        } else if (kt + 1 < NKI) cp_wait1();
        else                     cp_wait0();
        __syncthreads();

        const bf16* Sa = smb + (size_t)slot * STG_HALVES;
        const bf16* Sb = Sa + TBM * LDT;

        // prime fragments for ks=0
        #pragma unroll
        for (int i = 0; i < 4; i++)
            ldsm4(af[0][i][0], af[0][i][1], af[0][i][2], af[0][i][3],
                  Sa + (wm*64 + i*16 + a_row) * LDT + a_kof);
        #pragma unroll
        for (int j = 0; j < 4; j++) {
            uint32_t r0, r1, r2, r3;
            ldsm4(r0, r1, r2, r3,
                  Sb + (wn*64 + j*16 + b_row) * LDT + b_kof);
            bfr[0][j*2  ][0] = r0; bfr[0][j*2  ][1] = r1;
            bfr[0][j*2+1][0] = r2; bfr[0][j*2+1][1] = r3;
        }

        #pragma unroll
        for (int s = 0; s < TKC / 16; s++) {
            const int cb = s & 1, nb = cb ^ 1;
            if (s + 1 < TKC / 16) {
                const int ks = (s + 1) * 16;
                #pragma unroll
                for (int i = 0; i < 4; i++)
                    ldsm4(af[nb][i][0], af[nb][i][1], af[nb][i][2], af[nb][i][3],
                          Sa + (wm*64 + i*16 + a_row) * LDT + ks + a_kof);
                #pragma unroll
                for (int j = 0; j < 4; j++) {
                    uint32_t r0, r1, r2, r3;
                    ldsm4(r0, r1, r2, r3,
                          Sb + (wn*64 + j*16 + b_row) * LDT + ks + b_kof);
                    bfr[nb][j*2  ][0] = r0; bfr[nb][j*2  ][1] = r1;
                    bfr[nb][j*2+1][0] = r2; bfr[nb][j*2+1][1] = r3;
                }
            }
            #pragma unroll
            for (int i = 0; i < 4; i++)
                #pragma unroll
                for (int j = 0; j < 8; j++)
                    mma16816(acc[i][j], af[cb][i], bfr[cb][j]);
        }
        __syncthreads();
    }

    // ---- register epilogue ----
    bf16*  outb = (bf16*)outv;
    float* outf = (float*)outv;
    const int mbase = bm * TBM + wm * 64 + (lane >> 2);
    const int nbase = bn * TBN + wn * 64 + (lane & 3) * 2;
    #pragma unroll
    for (int i = 0; i < 4; i++) {
        #pragma unroll
        for (int j = 0; j < 8; j++) {
            const int n = nbase + j * 8;
            const float b0 = bias[n], b1 = bias[n + 1];
            #pragma unroll
            for (int half = 0; half < 2; half++) {
                const int m = mbase + i * 16 + half * 8;
                float v0 = (acc[i][j][half*2]     + b0) * scale;
                float v1 = (acc[i][j][half*2 + 1] + b1) * scale;
                if (mode == 0) {
                    __nv_bfloat162 p = __floats2bfloat162_rn(v0, v1);
                    *(__nv_bfloat162*)(outb + (size_t)m * Hh + n) = p;
                } else {
                    const float* rp = resid + (size_t)m * Hh + n;
                    float2 o; o.x = v0 + rp[0]; o.y = v1 + rp[1];
                    *(float2*)(outf + (size_t)m * Hh + n) = o;
                }
            }
        }
    }
}

// ============================================================================
// Flash cross-attention (WMMA bf16) — unchanged
// ============================================================================
typedef wmma::fragment<wmma::matrix_a, 16, 16, 16, bf16, wmma::row_major> AFrag;
typedef wmma::fragment<wmma::matrix_b, 16, 16, 16, bf16, wmma::col_major> BFragC;
typedef wmma::fragment<wmma::matrix_b, 16, 16, 16, bf16, wmma::row_major> BFragR;
typedef wmma::fragment<wmma::accumulator, 16, 16, 16, float>              CFrag;

#define BQt 64
#define BVt 64
#define LDQ 136
#define LDS_S 68
#define LDP 72
#define LDO 132
#define ATTN_SMEM (3*64*LDQ*2 + 64*LDS_S*4 + 64*LDP*2 + 64*LDO*4 + 64*4*3 + 64*4)

__global__ __launch_bounds__(256, 2) void attn_kernel(
    const bf16* __restrict__ Q, const bf16* __restrict__ K,
    const bf16* __restrict__ V, const int* __restrict__ amask,
    bf16* __restrict__ ctx)
{
    extern __shared__ char smraw[];
    bf16*  Qs = (bf16*)smraw;
    bf16*  Ks = Qs + 64*LDQ;
    bf16*  Vs = Ks + 64*LDQ;
    float* Ss = (float*)(Vs + 64*LDQ);
    bf16*  Ps = (bf16*)(Ss + 64*LDS_S);
    float* Os = (float*)(Ps + 64*LDP);
    float* mrow = Os + 64*LDO;
    float* lrow = mrow + 64;
    float* arow = lrow + 64;
    int*   msk  = (int*)(arow + 64);

    const int tid = threadIdx.x;
    const int warp = tid >> 5;
    const int wm = warp >> 1;
    const int wn = warp & 1;
    const int b = blockIdx.y >> 5, h = blockIdx.y & 31;
    const int lt = blockIdx.x;

    const bf16* Qb = Q + ((size_t)(b*Lq + lt*BQt)) * Hh + h*HDd;
    #pragma unroll
    for (int e = tid; e < 64*16; e += 256) {
        int r = e >> 4, c = (e & 15) * 8;
        *(uint4*)(Qs + r*LDQ + c) = *(const uint4*)(Qb + (size_t)r*Hh + c);
    }
    for (int e = tid; e < 64*LDO; e += 256) Os[e] = 0.0f;
    if (tid < 64) { mrow[tid] = -1e30f; lrow[tid] = 0.0f; }
    __syncthreads();

    #pragma unroll 1
    for (int jt = 0; jt < Vn / BVt; jt++) {
        const bf16* Kb = K + ((size_t)(b*Vn + jt*BVt)) * Hh + h*HDd;
        #pragma unroll
        for (int e = tid; e < 64*16; e += 256) {
            int r = e >> 4, c = (e & 15) * 8;
            *(uint4*)(Ks + r*LDQ + c) = *(const uint4*)(Kb + (size_t)r*Hh + c);
        }
        if (tid < 64) msk[tid] = amask[b*Vn + jt*BVt + tid];
        __syncthreads();

        {
            CFrag sacc[2];
            wmma::fill_fragment(sacc[0], 0.0f);
            wmma::fill_fragment(sacc[1], 0.0f);
            #pragma unroll
            for (int kk = 0; kk < HDd; kk += 16) {
                AFrag qa;
                wmma::load_matrix_sync(qa, Qs + (wm*16)*LDQ + kk, LDQ);
                #pragma unroll
                for (int j = 0; j < 2; j++) {
                    BFragC kb;
                    wmma::load_matrix_sync(kb, Ks + (wn*32 + j*16)*LDQ + kk, LDQ);
                    wmma::mma_sync(sacc[j], qa, kb, sacc[j]);
                }
            }
            #pragma unroll
            for (int j = 0; j < 2; j++)
                wmma::store_matrix_sync(Ss + (wm*16)*LDS_S + wn*32 + j*16, sacc[j],
                                        LDS_S, wmma::mem_row_major);
        }
        __syncthreads();

        const bf16* Vb = V + ((size_t)(b*Vn + jt*BVt)) * Hh + h*HDd;
        #pragma unroll
        for (int e = tid; e < 64*16; e += 256) {
            int r = e >> 4, c = (e & 15) * 8;
            *(uint4*)(Vs + r*LDQ + c) = *(const uint4*)(Vb + (size_t)r*Hh + c);
        }
        {
            const int row = tid >> 2, q = tid & 3;
            float vals[16];
            float mloc = -1e30f;
            #pragma unroll
            for (int c0 = 0; c0 < 16; c0++) {
                int c = q*16 + c0;
                float s = msk[c] ? Ss[row*LDS_S + c] : -1e30f;
                vals[c0] = s;
                mloc = fmaxf(mloc, s);
            }
            mloc = fmaxf(mloc, __shfl_xor_sync(0xffffffffu, mloc, 1));
            mloc = fmaxf(mloc, __shfl_xor_sync(0xffffffffu, mloc, 2));
            float mold = mrow[row];
            float mnew = fmaxf(mold, mloc);
            float ssum = 0.0f;
            #pragma unroll
            for (int c0 = 0; c0 < 16; c0++) {
                float p = __expf(vals[c0] - mnew);
                ssum += p;
                Ps[row*LDP + q*16 + c0] = __float2bfloat16(p);
            }
            ssum += __shfl_xor_sync(0xffffffffu, ssum, 1);
            ssum += __shfl_xor_sync(0xffffffffu, ssum, 2);
            if (q == 0) {
                float al = __expf(mold - mnew);
                arow[row] = al;
                lrow[row] = lrow[row] * al + ssum;
                mrow[row] = mnew;
            }
        }
        __syncthreads();

        #pragma unroll
        for (int e = tid; e < 64*32; e += 256) {
            int r = e >> 5, c4 = e & 31;
            float al = arow[r];
            float4 o = *(float4*)(Os + r*LDO + c4*4);
            o.x *= al; o.y *= al; o.z *= al; o.w *= al;
            *(float4*)(Os + r*LDO + c4*4) = o;
        }
        __syncthreads();

        {
            CFrag pv[4];
            #pragma unroll
            for (int j = 0; j < 4; j++)
                wmma::load_matrix_sync(pv[j], Os + (wm*16)*LDO + wn*64 + j*16,
                                       LDO, wmma::mem_row_major);
            #pragma unroll
            for (int kk = 0; kk < BVt; kk += 16) {
                AFrag pa;
                wmma::load_matrix_sync(pa, Ps + (wm*16)*LDP + kk, LDP);
                #pragma unroll
                for (int j = 0; j < 4; j++) {
                    BFragR vb_;
                    wmma::load_matrix_sync(vb_, Vs + kk*LDQ + wn*64 + j*16, LDQ);
                    wmma::mma_sync(pv[j], pa, vb_, pv[j]);
                }
            }
            #pragma unroll
            for (int j = 0; j < 4; j++)
                wmma::store_matrix_sync(Os + (wm*16)*LDO + wn*64 + j*16, pv[j],
                                        LDO, wmma::mem_row_major);
        }
        __syncthreads();
    }

    bf16* Cb = ctx + ((size_t)(b*Lq + lt*BQt)) * Hh + h*HDd;
    #pragma unroll
    for (int e = tid; e < 64*16; e += 256) {
        int r = e >> 4, c = (e & 15) * 8;
        float inv = 1.0f / lrow[r];
        bf16 tmp[8];
        #pragma unroll
        for (int u = 0; u < 8; u++)
            tmp[u] = __float2bfloat16(Os[r*LDO + c + u] * inv);
        *(uint4*)(Cb + (size_t)r*Hh + c) = *(uint4*)tmp;
    }
}

// ============================================================================
// LayerNorm over last dim (4096) per row
// ============================================================================
__global__ __launch_bounds__(256) void ln_kernel(
    const float* __restrict__ X, const float* __restrict__ g,
    const float* __restrict__ be, float* __restrict__ out)
{
    __shared__ float red[20];
    const int row = blockIdx.x, tid = threadIdx.x;
    const float* x = X + (size_t)row * Hh;
    float s = 0.0f, s2 = 0.0f;
    for (int i = tid; i < Hh; i += 256) { float v = x[i]; s += v; s2 += v*v; }
    #pragma unroll
    for (int o = 16; o; o >>= 1) {
        s  += __shfl_xor_sync(0xffffffffu, s,  o);
        s2 += __shfl_xor_sync(0xffffffffu, s2, o);
    }
    if ((tid & 31) == 0) { red[tid >> 5] = s; red[8 + (tid >> 5)] = s2; }
    __syncthreads();
    if (tid < 32) {
        float a = (tid < 8) ? red[tid] : 0.0f;
        float c = (tid < 8) ? red[8 + tid] : 0.0f;
        #pragma unroll
        for (int o = 4; o; o >>= 1) {
            a += __shfl_xor_sync(0xffffffffu, a, o);
            c += __shfl_xor_sync(0xffffffffu, c, o);
        }
        if (tid == 0) { red[16] = a; red[17] = c; }
    }
    __syncthreads();
    const float mu  = red[16] * (1.0f / Hh);
    const float var = red[17] * (1.0f / Hh) - mu*mu;
    const float inv = rsqrtf(var + 1e-5f);
    for (int i = tid; i < Hh; i += 256)
        out[(size_t)row * Hh + i] = (x[i] - mu) * inv * g[i] + be[i];
}

// ============================================================================
// host launcher
// ============================================================================
extern "C" void kernel_launch(void* const* d_in, const int* in_sizes, int n_in,
                              void* d_out, int out_size)
{
    const float* hidden = (const float*)d_in[0];
    const float* vision = (const float*)d_in[1];
    const int*   amask  = (const int*)  d_in[2];
    const float* Wq = (const float*)d_in[3];
    const float* bq = (const float*)d_in[4];
    const float* Wk = (const float*)d_in[5];
    const float* bk = (const float*)d_in[6];
    const float* Wv = (const float*)d_in[7];
    const float* bv = (const float*)d_in[8];
    const float* Wo = (const float*)d_in[9];
    const float* bo = (const float*)d_in[10];
    const float* lng = (const float*)d_in[11];
    const float* lnb = (const float*)d_in[12];
    float* out = (float*)d_out;

    bf16 *phb, *pvb, *pWq, *pWk, *pWv, *pWo, *pQ, *pK, *pV, *pCtx;
    float *pX;
    cudaGetSymbolAddress((void**)&phb, g_hb);
    cudaGetSymbolAddress((void**)&pvb, g_vb);
    cudaGetSymbolAddress((void**)&pWq, g_Wqb);
    cudaGetSymbolAddress((void**)&pWk, g_Wkb);
    cudaGetSymbolAddress((void**)&pWv, g_Wvb);
    cudaGetSymbolAddress((void**)&pWo, g_Wob);
    cudaGetSymbolAddress((void**)&pQ,  g_Qb);
    cudaGetSymbolAddress((void**)&pK,  g_Kb);
    cudaGetSymbolAddress((void**)&pV,  g_Vb);
    cudaGetSymbolAddress((void**)&pCtx, g_ctx);
    cudaGetSymbolAddress((void**)&pX,  g_X);

    cudaFuncSetAttribute(gemm_mma,    cudaFuncAttributeMaxDynamicSharedMemorySize, GEMM_SMEM);
    cudaFuncSetAttribute(attn_kernel, cudaFuncAttributeMaxDynamicSharedMemorySize, ATTN_SMEM);

    const long long total4 = (long long)CONV_TOTAL;
    f2bf_all<<<(unsigned)((total4 + 255) / 256), 256>>>(
        hidden, vision, Wq, Wk, Wv, Wo, phb, pvb, pWq, pWk, pWv, pWo);

    dim3 gb(Hh / TBN, Mrows / TBM);      // (16, 16)
    dim3 tb(256);

    gemm_mma<<<gb, tb, GEMM_SMEM>>>(phb, pWq, bq, nullptr, pQ, QSCALE, 0);
    gemm_mma<<<gb, tb, GEMM_SMEM>>>(pvb, pWk, bk, nullptr, pK, 1.0f, 0);
    gemm_mma<<<gb, tb, GEMM_SMEM>>>(pvb, pWv, bv, nullptr, pV, 1.0f, 0);
    attn_kernel<<<dim3(Lq / BQt, Bb * NHh), tb, ATTN_SMEM>>>(pQ, pK, pV, amask, pCtx);
    gemm_mma<<<gb, tb, GEMM_SMEM>>>(pCtx, pWo, bo, hidden, pX, 1.0f, 2);
    ln_kernel<<<Mrows, tb>>>(pX, lng, lnb, out);
}

// round 7
// speedup vs baseline: 4.4117x; 1.1715x over previous
#include <cuda_runtime.h>
#include <cuda_bf16.h>
#include <math.h>
#include <cstdint>

typedef __nv_bfloat16 bf16;

// ---------------- problem constants ----------------
#define Bb   2
#define Lq   1024
#define Vn   1024
#define Hh   4096
#define NHh  32
#define HDd  128
#define Mrows (Bb*Lq)          // 2048
#define QSCALE 0.08838834764831845f   // 1/sqrt(128)

// ---------------- scratch (device globals) ----------------------------------
__device__ bf16  g_hb [(size_t)Mrows*Hh];
__device__ bf16  g_vb [(size_t)Mrows*Hh];
__device__ bf16  g_Wqb[(size_t)Hh*Hh];
__device__ bf16  g_Wkb[(size_t)Hh*Hh];
__device__ bf16  g_Wvb[(size_t)Hh*Hh];
__device__ bf16  g_Wob[(size_t)Hh*Hh];
__device__ bf16  g_Qb [(size_t)Mrows*Hh];
__device__ bf16  g_Kb [(size_t)Mrows*Hh];
__device__ bf16  g_Vb [(size_t)Mrows*Hh];
__device__ bf16  g_ctx[(size_t)Mrows*Hh];
__device__ float g_X  [(size_t)Mrows*Hh];

// ---------------- low-level helpers -----------------------------------------
__device__ __forceinline__ void cpasync16(void* sdst, const void* gsrc) {
    unsigned s = (unsigned)__cvta_generic_to_shared(sdst);
    asm volatile("cp.async.cg.shared.global [%0], [%1], 16;" :: "r"(s), "l"(gsrc));
}
__device__ __forceinline__ void cp_commit() { asm volatile("cp.async.commit_group;"); }
__device__ __forceinline__ void cp_wait2()  { asm volatile("cp.async.wait_group 2;"); }
__device__ __forceinline__ void cp_wait1()  { asm volatile("cp.async.wait_group 1;"); }
__device__ __forceinline__ void cp_wait0()  { asm volatile("cp.async.wait_group 0;"); }

__device__ __forceinline__ void ldsm4(uint32_t& r0, uint32_t& r1, uint32_t& r2, uint32_t& r3,
                                      const void* p) {
    unsigned a = (unsigned)__cvta_generic_to_shared(p);
    asm volatile("ldmatrix.sync.aligned.m8n8.x4.shared.b16 {%0,%1,%2,%3}, [%4];"
                 : "=r"(r0), "=r"(r1), "=r"(r2), "=r"(r3) : "r"(a));
}
__device__ __forceinline__ void ldsm4t(uint32_t& r0, uint32_t& r1, uint32_t& r2, uint32_t& r3,
                                       const void* p) {
    unsigned a = (unsigned)__cvta_generic_to_shared(p);
    asm volatile("ldmatrix.sync.aligned.m8n8.x4.trans.shared.b16 {%0,%1,%2,%3}, [%4];"
                 : "=r"(r0), "=r"(r1), "=r"(r2), "=r"(r3) : "r"(a));
}

__device__ __forceinline__ void mma16816(float* c, const uint32_t* a, const uint32_t* b) {
    asm volatile(
        "mma.sync.aligned.m16n8k16.row.col.f32.bf16.bf16.f32 "
        "{%0,%1,%2,%3}, {%4,%5,%6,%7}, {%8,%9}, {%0,%1,%2,%3};"
        : "+f"(c[0]), "+f"(c[1]), "+f"(c[2]), "+f"(c[3])
        : "r"(a[0]), "r"(a[1]), "r"(a[2]), "r"(a[3]), "r"(b[0]), "r"(b[1]));
}

// ============================================================================
// fused fp32 -> bf16 conversion for all 6 tensors
// ============================================================================
#define A4 ((size_t)Mrows*Hh/4)   // 2M float4
#define W4 ((size_t)Hh*Hh/4)      // 4M float4
#define CONV_TOTAL (2*A4 + 4*W4)  // 20M float4

__global__ __launch_bounds__(256) void f2bf_all(
    const float* __restrict__ h, const float* __restrict__ v,
    const float* __restrict__ wq, const float* __restrict__ wk,
    const float* __restrict__ wv, const float* __restrict__ wo,
    bf16* __restrict__ dh, bf16* __restrict__ dv,
    bf16* __restrict__ dwq, bf16* __restrict__ dwk,
    bf16* __restrict__ dwv, bf16* __restrict__ dwo)
{
    size_t i = (size_t)blockIdx.x * 256 + threadIdx.x;
    if (i >= CONV_TOTAL) return;
    const float* src; bf16* dst; size_t off;
    if (i < A4)            { src = h;  dst = dh;  off = i; }
    else if (i < 2*A4)     { src = v;  dst = dv;  off = i - A4; }
    else {
        size_t j = i - 2*A4;
        int w = (int)(j >> 22);          // W4 = 1<<22
        off = j & (W4 - 1);
        src = (w == 0) ? wq : (w == 1) ? wk : (w == 2) ? wv : wo;
        dst = (w == 0) ? dwq : (w == 1) ? dwk : (w == 2) ? dwv : dwo;
    }
    float4 x = ((const float4*)src)[off];
    __nv_bfloat162 a = __floats2bfloat162_rn(x.x, x.y);
    __nv_bfloat162 b = __floats2bfloat162_rn(x.z, x.w);
    uint2 p; p.x = *(unsigned*)&a; p.y = *(unsigned*)&b;
    ((uint2*)dst)[off] = p;
}

// ============================================================================
// mma.sync bf16 GEMM — unchanged from round 6
// ============================================================================
#define TBM 128
#define TBN 256
#define TKC 64
#define NST 3
#define LDT 72
#define STG_HALVES ((TBM+TBN)*LDT)
#define GEMM_SMEM (NST*STG_HALVES*2)
#define NKI (Hh / TKC)

__device__ __forceinline__ void load_stage(bf16* smb, const bf16* Ab, const bf16* Wb,
                                           int slot, int k0, int tid)
{
    bf16* Sa = smb + (size_t)slot * STG_HALVES;
    bf16* Sb = Sa + TBM * LDT;
    #pragma unroll
    for (int i = 0; i < 4; i++) {
        int ch = tid + i * 256, r = ch >> 3, c = ch & 7;
        cpasync16(Sa + r * LDT + c * 8, Ab + (size_t)r * Hh + k0 + c * 8);
    }
    #pragma unroll
    for (int i = 0; i < 8; i++) {
        int ch = tid + i * 256, r = ch >> 3, c = ch & 7;
        cpasync16(Sb + r * LDT + c * 8, Wb + (size_t)r * Hh + k0 + c * 8);
    }
    cp_commit();
}

__global__ __launch_bounds__(256, 1) void gemm_mma(
    const bf16* __restrict__ A, const bf16* __restrict__ W,
    const float* __restrict__ bias, const float* __restrict__ resid,
    void* __restrict__ outv, float scale, int mode)
{
    extern __shared__ bf16 smb[];
    const int tid = threadIdx.x, warp = tid >> 5, lane = tid & 31;
    const int wm = warp >> 2;
    const int wn = warp & 3;
    const int bn = blockIdx.x, bm = blockIdx.y;

    const bf16* Ab = A + (size_t)(bm * TBM) * Hh;
    const bf16* Wb = W + (size_t)(bn * TBN) * Hh;

    float acc[4][8][4];
    #pragma unroll
    for (int i = 0; i < 4; i++)
        #pragma unroll
        for (int j = 0; j < 8; j++)
            #pragma unroll
            for (int e = 0; e < 4; e++) acc[i][j][e] = 0.0f;

    load_stage(smb, Ab, Wb, 0, 0, tid);
    load_stage(smb, Ab, Wb, 1, TKC, tid);

    const int a_row = (lane & 15);
    const int a_kof = (lane >> 4) * 8;
    const int b_row = (lane & 7) + ((lane >> 4) * 8);
    const int b_kof = ((lane >> 3) & 1) * 8;

    uint32_t af[2][4][4];
    uint32_t bfr[2][8][2];

    #pragma unroll 1
    for (int kt = 0; kt < NKI; kt++) {
        const int slot = kt % NST;
        if (kt + 2 < NKI) {
            load_stage(smb, Ab, Wb, (kt + 2) % NST, (kt + 2) * TKC, tid);
            cp_wait2();
        } else if (kt + 1 < NKI) cp_wait1();
        else                     cp_wait0();
        __syncthreads();

        const bf16* Sa = smb + (size_t)slot * STG_HALVES;
        const bf16* Sb = Sa + TBM * LDT;

        #pragma unroll
        for (int i = 0; i < 4; i++)
            ldsm4(af[0][i][0], af[0][i][1], af[0][i][2], af[0][i][3],
                  Sa + (wm*64 + i*16 + a_row) * LDT + a_kof);
        #pragma unroll
        for (int j = 0; j < 4; j++) {
            uint32_t r0, r1, r2, r3;
            ldsm4(r0, r1, r2, r3,
                  Sb + (wn*64 + j*16 + b_row) * LDT + b_kof);
            bfr[0][j*2  ][0] = r0; bfr[0][j*2  ][1] = r1;
            bfr[0][j*2+1][0] = r2; bfr[0][j*2+1][1] = r3;
        }

        #pragma unroll
        for (int s = 0; s < TKC / 16; s++) {
            const int cb = s & 1, nb = cb ^ 1;
            if (s + 1 < TKC / 16) {
                const int ks = (s + 1) * 16;
                #pragma unroll
                for (int i = 0; i < 4; i++)
                    ldsm4(af[nb][i][0], af[nb][i][1], af[nb][i][2], af[nb][i][3],
                          Sa + (wm*64 + i*16 + a_row) * LDT + ks + a_kof);
                #pragma unroll
                for (int j = 0; j < 4; j++) {
                    uint32_t r0, r1, r2, r3;
                    ldsm4(r0, r1, r2, r3,
                          Sb + (wn*64 + j*16 + b_row) * LDT + ks + b_kof);
                    bfr[nb][j*2  ][0] = r0; bfr[nb][j*2  ][1] = r1;
                    bfr[nb][j*2+1][0] = r2; bfr[nb][j*2+1][1] = r3;
                }
            }
            #pragma unroll
            for (int i = 0; i < 4; i++)
                #pragma unroll
                for (int j = 0; j < 8; j++)
                    mma16816(acc[i][j], af[cb][i], bfr[cb][j]);
        }
        __syncthreads();
    }

    bf16*  outb = (bf16*)outv;
    float* outf = (float*)outv;
    const int mbase = bm * TBM + wm * 64 + (lane >> 2);
    const int nbase = bn * TBN + wn * 64 + (lane & 3) * 2;
    #pragma unroll
    for (int i = 0; i < 4; i++) {
        #pragma unroll
        for (int j = 0; j < 8; j++) {
            const int n = nbase + j * 8;
            const float b0 = bias[n], b1 = bias[n + 1];
            #pragma unroll
            for (int half = 0; half < 2; half++) {
                const int m = mbase + i * 16 + half * 8;
                float v0 = (acc[i][j][half*2]     + b0) * scale;
                float v1 = (acc[i][j][half*2 + 1] + b1) * scale;
                if (mode == 0) {
                    __nv_bfloat162 p = __floats2bfloat162_rn(v0, v1);
                    *(__nv_bfloat162*)(outb + (size_t)m * Hh + n) = p;
                } else {
                    const float* rp = resid + (size_t)m * Hh + n;
                    float2 o; o.x = v0 + rp[0]; o.y = v1 + rp[1];
                    *(float2*)(outf + (size_t)m * Hh + n) = o;
                }
            }
        }
    }
}

// ============================================================================
// Flash cross-attention v3: mma.sync, register-resident S/P/O, cp.async K/V.
// CTA: 64 q x one (b,h). 8 warps: wm=warp>>1 (q16 group), wn=warp&1.
//  S phase: warp tile 16q x 32kv.  PV phase: warp tile 16q x 64d (full kv).
// ============================================================================
#define LDK 136               // halves per K/V/Q row (128 + 8)
#define LDP2 72               // halves per P row
// halves: Qs 64*136 + 2 stages * 2*64*136 + Ps 64*72 ; floats: pm/ps/bias 3*128
#define ATTN3_SMEM ((64*LDK + 2*2*64*LDK + 64*LDP2)*2 + 3*128*4)   // 97792

__global__ __launch_bounds__(256, 2) void attn3(
    const bf16* __restrict__ Q, const bf16* __restrict__ K,
    const bf16* __restrict__ V, const int* __restrict__ amask,
    bf16* __restrict__ ctx)
{
    extern __shared__ char smr[];
    bf16*  Qs  = (bf16*)smr;                       // [64][136]
    bf16*  KVs = Qs + 64*LDK;                      // 2 stages x {K[64][136], V[64][136]}
    bf16*  Ps  = KVs + 2*2*64*LDK;                 // [64][72]
    float* pm    = (float*)(Ps + 64*LDP2);         // [2][64] partial row max
    float* psum  = pm + 128;                       // [2][64] partial row sum
    float* sbias = psum + 128;                     // [2][64] mask bias (per stage)

    const int tid = threadIdx.x, warp = tid >> 5, lane = tid & 31;
    const int wm = warp >> 1;                      // 0..3
    const int wn = warp & 1;                       // 0..1
    const int b = blockIdx.y >> 5, h = blockIdx.y & 31;
    const int lt = blockIdx.x;

    const int r0 = lane >> 2;                      // row within 16 (and +8)
    const int qp = lane & 3;                       // quad position (col pairs)
    const int a_row = lane & 15;
    const int a_kof = (lane >> 4) * 8;
    const int b_row = (lane & 7) + ((lane >> 4) * 8);
    const int b_kof = ((lane >> 3) & 1) * 8;

    // ---- load Q tile (plain), issue stage 0 K/V, mask bias 0 ----
    const bf16* Qb = Q + ((size_t)(b*Lq + lt*64)) * Hh + h*HDd;
    #pragma unroll
    for (int e = tid; e < 64*16; e += 256) {
        int r = e >> 4, c = (e & 15) * 8;
        *(uint4*)(Qs + r*LDK + c) = *(const uint4*)(Qb + (size_t)r*Hh + c);
    }
    {
        bf16* Ks0 = KVs;
        bf16* Vs0 = KVs + 64*LDK;
        const bf16* Kb = K + ((size_t)(b*Vn)) * Hh + h*HDd;
        const bf16* Vb = V + ((size_t)(b*Vn)) * Hh + h*HDd;
        #pragma unroll
        for (int i = 0; i < 4; i++) {
            int ch = tid + i * 256, r = ch >> 4, c = (ch & 15) * 8;
            cpasync16(Ks0 + r*LDK + c, Kb + (size_t)r*Hh + c);
        }
        #pragma unroll
        for (int i = 0; i < 4; i++) {
            int ch = tid + i * 256, r = ch >> 4, c = (ch & 15) * 8;
            cpasync16(Vs0 + r*LDK + c, Vb + (size_t)r*Hh + c);
        }
        cp_commit();
        if (tid < 64) sbias[tid] = amask[b*Vn + tid] ? 0.0f : -1e30f;
    }
    __syncthreads();   // Qs visible

    // ---- resident Q a-frags: 8 k16 tiles ----
    uint32_t qa[8][4];
    #pragma unroll
    for (int k = 0; k < 8; k++)
        ldsm4(qa[k][0], qa[k][1], qa[k][2], qa[k][3],
              Qs + (wm*16 + a_row) * LDK + k*16 + a_kof);

    float oacc[8][4];
    #pragma unroll
    for (int j = 0; j < 8; j++)
        #pragma unroll
        for (int e = 0; e < 4; e++) oacc[j][e] = 0.0f;
    float mrun0 = -1e30f, mrun1 = -1e30f, l0 = 0.0f, l1 = 0.0f;

    #pragma unroll 1
    for (int jt = 0; jt < Vn/64; jt++) {
        const int st = jt & 1;
        cp_wait0();
        __syncthreads();      // stage st ready; all warps done with previous PV

        // issue next stage (overwrites stage of jt-1, freed by barrier above)
        if (jt + 1 < Vn/64) {
            const int ns = st ^ 1;
            bf16* Ksn = KVs + ns*2*64*LDK;
            bf16* Vsn = Ksn + 64*LDK;
            const bf16* Kb = K + ((size_t)(b*Vn + (jt+1)*64)) * Hh + h*HDd;
            const bf16* Vb = V + ((size_t)(b*Vn + (jt+1)*64)) * Hh + h*HDd;
            #pragma unroll
            for (int i = 0; i < 4; i++) {
                int ch = tid + i * 256, r = ch >> 4, c = (ch & 15) * 8;
                cpasync16(Ksn + r*LDK + c, Kb + (size_t)r*Hh + c);
            }
            #pragma unroll
            for (int i = 0; i < 4; i++) {
                int ch = tid + i * 256, r = ch >> 4, c = (ch & 15) * 8;
                cpasync16(Vsn + r*LDK + c, Vb + (size_t)r*Hh + c);
            }
            cp_commit();
            if (tid < 64) sbias[(st^1)*64 + tid] =
                amask[b*Vn + (jt+1)*64 + tid] ? 0.0f : -1e30f;
        }

        const bf16* Ksb = KVs + st*2*64*LDK;
        const bf16* Vsb = Ksb + 64*LDK;

        // ---- S = Q K^T : warp tile 16 x 32 (4 n8 tiles, 8 k16) ----
        float sacc[4][4];
        #pragma unroll
        for (int t = 0; t < 4; t++)
            #pragma unroll
            for (int e = 0; e < 4; e++) sacc[t][e] = 0.0f;
        #pragma unroll
        for (int k = 0; k < 8; k++) {
            #pragma unroll
            for (int g = 0; g < 2; g++) {
                uint32_t u0, u1, u2, u3;
                ldsm4(u0, u1, u2, u3,
                      Ksb + (wn*32 + g*16 + b_row) * LDK + k*16 + b_kof);
                uint32_t bb0[2] = {u0, u1}, bb1[2] = {u2, u3};
                mma16816(sacc[g*2  ], qa[k], bb0);
                mma16816(sacc[g*2+1], qa[k], bb1);
            }
        }

        // ---- softmax (register) ----
        float m0 = -1e30f, m1 = -1e30f;
        #pragma unroll
        for (int t = 0; t < 4; t++) {
            const int c0 = wn*32 + t*8 + qp*2;
            float bi0 = sbias[st*64 + c0], bi1 = sbias[st*64 + c0 + 1];
            sacc[t][0] += bi0; sacc[t][1] += bi1;
            sacc[t][2] += bi0; sacc[t][3] += bi1;
            m0 = fmaxf(m0, fmaxf(sacc[t][0], sacc[t][1]));
            m1 = fmaxf(m1, fmaxf(sacc[t][2], sacc[t][3]));
        }
        m0 = fmaxf(m0, __shfl_xor_sync(0xffffffffu, m0, 1));
        m0 = fmaxf(m0, __shfl_xor_sync(0xffffffffu, m0, 2));
        m1 = fmaxf(m1, __shfl_xor_sync(0xffffffffu, m1, 1));
        m1 = fmaxf(m1, __shfl_xor_sync(0xffffffffu, m1, 2));
        if (qp == 0) {
            pm[wn*64 + wm*16 + r0]     = m0;
            pm[wn*64 + wm*16 + r0 + 8] = m1;
        }
        __syncthreads();
        float mt0 = fmaxf(m0, pm[(wn^1)*64 + wm*16 + r0]);
        float mt1 = fmaxf(m1, pm[(wn^1)*64 + wm*16 + r0 + 8]);
        float mn0 = fmaxf(mrun0, mt0), mn1 = fmaxf(mrun1, mt1);
        float al0 = __expf(mrun0 - mn0), al1 = __expf(mrun1 - mn1);
        mrun0 = mn0; mrun1 = mn1;

        float s0 = 0.0f, s1 = 0.0f;
        #pragma unroll
        for (int t = 0; t < 4; t++) {
            float p00 = __expf(sacc[t][0] - mn0), p01 = __expf(sacc[t][1] - mn0);
            float p10 = __expf(sacc[t][2] - mn1), p11 = __expf(sacc[t][3] - mn1);
            s0 += p00 + p01; s1 += p10 + p11;
            __nv_bfloat162 w0 = __floats2bfloat162_rn(p00, p01);
            __nv_bfloat162 w1 = __floats2bfloat162_rn(p10, p11);
            const int c0 = wn*32 + t*8 + qp*2;
            *(__nv_bfloat162*)(Ps + (wm*16 + r0)     * LDP2 + c0) = w0;
            *(__nv_bfloat162*)(Ps + (wm*16 + r0 + 8) * LDP2 + c0) = w1;
        }
        s0 += __shfl_xor_sync(0xffffffffu, s0, 1);
        s0 += __shfl_xor_sync(0xffffffffu, s0, 2);
        s1 += __shfl_xor_sync(0xffffffffu, s1, 1);
        s1 += __shfl_xor_sync(0xffffffffu, s1, 2);
        if (qp == 0) {
            psum[wn*64 + wm*16 + r0]     = s0;
            psum[wn*64 + wm*16 + r0 + 8] = s1;
        }
        // rescale O + l by alpha while waiting
        #pragma unroll
        for (int j = 0; j < 8; j++) {
            oacc[j][0] *= al0; oacc[j][1] *= al0;
            oacc[j][2] *= al1; oacc[j][3] *= al1;
        }
        l0 *= al0; l1 *= al1;
        __syncthreads();
        l0 += psum[wm*16 + r0]     + psum[64 + wm*16 + r0];
        l1 += psum[wm*16 + r0 + 8] + psum[64 + wm*16 + r0 + 8];

        // ---- O += P V : warp tile 16q x 64d (8 n8 tiles, 4 k16 over kv) ----
        uint32_t pa[4][4];
        #pragma unroll
        for (int kt = 0; kt < 4; kt++)
            ldsm4(pa[kt][0], pa[kt][1], pa[kt][2], pa[kt][3],
                  Ps + (wm*16 + a_row) * LDP2 + kt*16 + a_kof);
        #pragma unroll
        for (int kt = 0; kt < 4; kt++) {
            #pragma unroll
            for (int g = 0; g < 4; g++) {
                uint32_t u0, u1, u2, u3;
                ldsm4t(u0, u1, u2, u3,
                       Vsb + (kt*16 + a_row) * LDK + wn*64 + g*16 + a_kof);
                uint32_t bb0[2] = {u0, u1}, bb1[2] = {u2, u3};
                mma16816(oacc[g*2  ], pa[kt], bb0);
                mma16816(oacc[g*2+1], pa[kt], bb1);
            }
        }
    }

    // ---- write ctx = O / l ----
    const float i0 = 1.0f / l0, i1 = 1.0f / l1;
    bf16* Cb = ctx + ((size_t)(b*Lq + lt*64 + wm*16)) * Hh + h*HDd;
    #pragma unroll
    for (int j = 0; j < 8; j++) {
        const int n = wn*64 + j*8 + qp*2;
        __nv_bfloat162 w0 = __floats2bfloat162_rn(oacc[j][0]*i0, oacc[j][1]*i0);
        __nv_bfloat162 w1 = __floats2bfloat162_rn(oacc[j][2]*i1, oacc[j][3]*i1);
        *(__nv_bfloat162*)(Cb + (size_t)(r0)     * Hh + n) = w0;
        *(__nv_bfloat162*)(Cb + (size_t)(r0 + 8) * Hh + n) = w1;
    }
}

// ============================================================================
// LayerNorm over last dim (4096) per row
// ============================================================================
__global__ __launch_bounds__(256) void ln_kernel(
    const float* __restrict__ X, const float* __restrict__ g,
    const float* __restrict__ be, float* __restrict__ out)
{
    __shared__ float red[20];
    const int row = blockIdx.x, tid = threadIdx.x;
    const float* x = X + (size_t)row * Hh;
    float s = 0.0f, s2 = 0.0f;
    for (int i = tid; i < Hh; i += 256) { float v = x[i]; s += v; s2 += v*v; }
    #pragma unroll
    for (int o = 16; o; o >>= 1) {
        s  += __shfl_xor_sync(0xffffffffu, s,  o);
        s2 += __shfl_xor_sync(0xffffffffu, s2, o);
    }
    if ((tid & 31) == 0) { red[tid >> 5] = s; red[8 + (tid >> 5)] = s2; }
    __syncthreads();
    if (tid < 32) {
        float a = (tid < 8) ? red[tid] : 0.0f;
        float c = (tid < 8) ? red[8 + tid] : 0.0f;
        #pragma unroll
        for (int o = 4; o; o >>= 1) {
            a += __shfl_xor_sync(0xffffffffu, a, o);
            c += __shfl_xor_sync(0xffffffffu, c, o);
        }
        if (tid == 0) { red[16] = a; red[17] = c; }
    }
    __syncthreads();
    const float mu  = red[16] * (1.0f / Hh);
    const float var = red[17] * (1.0f / Hh) - mu*mu;
    const float inv = rsqrtf(var + 1e-5f);
    for (int i = tid; i < Hh; i += 256)
        out[(size_t)row * Hh + i] = (x[i] - mu) * inv * g[i] + be[i];
}

// ============================================================================
// host launcher
// ============================================================================
extern "C" void kernel_launch(void* const* d_in, const int* in_sizes, int n_in,
                              void* d_out, int out_size)
{
    const float* hidden = (const float*)d_in[0];
    const float* vision = (const float*)d_in[1];
    const int*   amask  = (const int*)  d_in[2];
    const float* Wq = (const float*)d_in[3];
    const float* bq = (const float*)d_in[4];
    const float* Wk = (const float*)d_in[5];
    const float* bk = (const float*)d_in[6];
    const float* Wv = (const float*)d_in[7];
    const float* bv = (const float*)d_in[8];
    const float* Wo = (const float*)d_in[9];
    const float* bo = (const float*)d_in[10];
    const float* lng = (const float*)d_in[11];
    const float* lnb = (const float*)d_in[12];
    float* out = (float*)d_out;

    bf16 *phb, *pvb, *pWq, *pWk, *pWv, *pWo, *pQ, *pK, *pV, *pCtx;
    float *pX;
    cudaGetSymbolAddress((void**)&phb, g_hb);
    cudaGetSymbolAddress((void**)&pvb, g_vb);
    cudaGetSymbolAddress((void**)&pWq, g_Wqb);
    cudaGetSymbolAddress((void**)&pWk, g_Wkb);
    cudaGetSymbolAddress((void**)&pWv, g_Wvb);
    cudaGetSymbolAddress((void**)&pWo, g_Wob);
    cudaGetSymbolAddress((void**)&pQ,  g_Qb);
    cudaGetSymbolAddress((void**)&pK,  g_Kb);
    cudaGetSymbolAddress((void**)&pV,  g_Vb);
    cudaGetSymbolAddress((void**)&pCtx, g_ctx);
    cudaGetSymbolAddress((void**)&pX,  g_X);

    cudaFuncSetAttribute(gemm_mma, cudaFuncAttributeMaxDynamicSharedMemorySize, GEMM_SMEM);
    cudaFuncSetAttribute(attn3,    cudaFuncAttributeMaxDynamicSharedMemorySize, ATTN3_SMEM);

    const long long total4 = (long long)CONV_TOTAL;
    f2bf_all<<<(unsigned)((total4 + 255) / 256), 256>>>(
        hidden, vision, Wq, Wk, Wv, Wo, phb, pvb, pWq, pWk, pWv, pWo);

    dim3 gb(Hh / TBN, Mrows / TBM);      // (16, 16)
    dim3 tb(256);

    gemm_mma<<<gb, tb, GEMM_SMEM>>>(phb, pWq, bq, nullptr, pQ, QSCALE, 0);
    gemm_mma<<<gb, tb, GEMM_SMEM>>>(pvb, pWk, bk, nullptr, pK, 1.0f, 0);
    gemm_mma<<<gb, tb, GEMM_SMEM>>>(pvb, pWv, bv, nullptr, pV, 1.0f, 0);
    attn3<<<dim3(Lq / 64, Bb * NHh), tb, ATTN3_SMEM>>>(pQ, pK, pV, amask, pCtx);
    gemm_mma<<<gb, tb, GEMM_SMEM>>>(pCtx, pWo, bo, hidden, pX, 1.0f, 2);
    ln_kernel<<<Mrows, tb>>>(pX, lng, lnb, out);
}

// round 8
// speedup vs baseline: 4.7475x; 1.0761x over previous
#include <cuda_runtime.h>
#include <cuda_bf16.h>
#include <math.h>
#include <cstdint>

typedef __nv_bfloat16 bf16;

// ---------------- problem constants ----------------
#define Bb   2
#define Lq   1024
#define Vn   1024
#define Hh   4096
#define NHh  32
#define HDd  128
#define Mrows (Bb*Lq)          // 2048
#define QSCALE 0.08838834764831845f   // 1/sqrt(128)

// ---------------- scratch (device globals) ----------------------------------
__device__ bf16  g_hb [(size_t)Mrows*Hh];
__device__ bf16  g_vb [(size_t)Mrows*Hh];
__device__ bf16  g_Wqb[(size_t)Hh*Hh];
__device__ bf16  g_Wkb[(size_t)Hh*Hh];
__device__ bf16  g_Wvb[(size_t)Hh*Hh];
__device__ bf16  g_Wob[(size_t)Hh*Hh];
__device__ bf16  g_Qb [(size_t)Mrows*Hh];
__device__ bf16  g_Kb [(size_t)Mrows*Hh];
__device__ bf16  g_Vb [(size_t)Mrows*Hh];
__device__ bf16  g_ctx[(size_t)Mrows*Hh];
__device__ float g_X  [(size_t)Mrows*Hh];

// ---------------- low-level helpers -----------------------------------------
__device__ __forceinline__ void cpasync16(void* sdst, const void* gsrc) {
    unsigned s = (unsigned)__cvta_generic_to_shared(sdst);
    asm volatile("cp.async.cg.shared.global [%0], [%1], 16;" :: "r"(s), "l"(gsrc));
}
__device__ __forceinline__ void cp_commit() { asm volatile("cp.async.commit_group;"); }
__device__ __forceinline__ void cp_wait1()  { asm volatile("cp.async.wait_group 1;"); }
__device__ __forceinline__ void cp_wait0()  { asm volatile("cp.async.wait_group 0;"); }

__device__ __forceinline__ void ldsm4(uint32_t& r0, uint32_t& r1, uint32_t& r2, uint32_t& r3,
                                      const void* p) {
    unsigned a = (unsigned)__cvta_generic_to_shared(p);
    asm volatile("ldmatrix.sync.aligned.m8n8.x4.shared.b16 {%0,%1,%2,%3}, [%4];"
                 : "=r"(r0), "=r"(r1), "=r"(r2), "=r"(r3) : "r"(a));
}
__device__ __forceinline__ void ldsm4t(uint32_t& r0, uint32_t& r1, uint32_t& r2, uint32_t& r3,
                                       const void* p) {
    unsigned a = (unsigned)__cvta_generic_to_shared(p);
    asm volatile("ldmatrix.sync.aligned.m8n8.x4.trans.shared.b16 {%0,%1,%2,%3}, [%4];"
                 : "=r"(r0), "=r"(r1), "=r"(r2), "=r"(r3) : "r"(a));
}

__device__ __forceinline__ void mma16816(float* c, const uint32_t* a, const uint32_t* b) {
    asm volatile(
        "mma.sync.aligned.m16n8k16.row.col.f32.bf16.bf16.f32 "
        "{%0,%1,%2,%3}, {%4,%5,%6,%7}, {%8,%9}, {%0,%1,%2,%3};"
        : "+f"(c[0]), "+f"(c[1]), "+f"(c[2]), "+f"(c[3])
        : "r"(a[0]), "r"(a[1]), "r"(a[2]), "r"(a[3]), "r"(b[0]), "r"(b[1]));
}

// ============================================================================
// fused fp32 -> bf16 conversion for all 6 tensors
// ============================================================================
#define A4 ((size_t)Mrows*Hh/4)   // 2M float4
#define W4 ((size_t)Hh*Hh/4)      // 4M float4
#define CONV_TOTAL (2*A4 + 4*W4)  // 20M float4

__global__ __launch_bounds__(256) void f2bf_all(
    const float* __restrict__ h, const float* __restrict__ v,
    const float* __restrict__ wq, const float* __restrict__ wk,
    const float* __restrict__ wv, const float* __restrict__ wo,
    bf16* __restrict__ dh, bf16* __restrict__ dv,
    bf16* __restrict__ dwq, bf16* __restrict__ dwk,
    bf16* __restrict__ dwv, bf16* __restrict__ dwo)
{
    size_t i = (size_t)blockIdx.x * 256 + threadIdx.x;
    if (i >= CONV_TOTAL) return;
    const float* src; bf16* dst; size_t off;
    if (i < A4)            { src = h;  dst = dh;  off = i; }
    else if (i < 2*A4)     { src = v;  dst = dv;  off = i - A4; }
    else {
        size_t j = i - 2*A4;
        int w = (int)(j >> 22);          // W4 = 1<<22
        off = j & (W4 - 1);
        src = (w == 0) ? wq : (w == 1) ? wk : (w == 2) ? wv : wo;
        dst = (w == 0) ? dwq : (w == 1) ? dwk : (w == 2) ? dwv : dwo;
    }
    float4 x = ((const float4*)src)[off];
    __nv_bfloat162 a = __floats2bfloat162_rn(x.x, x.y);
    __nv_bfloat162 b = __floats2bfloat162_rn(x.z, x.w);
    uint2 p; p.x = *(unsigned*)&a; p.y = *(unsigned*)&b;
    ((uint2*)dst)[off] = p;
}

// ============================================================================
// mma.sync bf16 GEMM: out = (A[M,K] @ W[N,K]^T + bias) * scale (+resid)
// CTA tile 128x256, BK=64, NST=4 cp.async stages, 8 warps (2x4), warp 64x64.
// Flat k16 pipeline with cross-chunk fragment prefetch (no per-chunk prime).
// ============================================================================
#define TBM 128
#define TBN 256
#define TKC 64
#define NST 4
#define LDT 72
#define STG_HALVES ((TBM+TBN)*LDT)              // 27648
#define GEMM_SMEM (NST*STG_HALVES*2)            // 221184 bytes
#define NKI (Hh / TKC)                          // 64

__device__ __forceinline__ void load_stage(bf16* smb, const bf16* Ab, const bf16* Wb,
                                           int slot, int k0, int tid)
{
    bf16* Sa = smb + (size_t)slot * STG_HALVES;
    bf16* Sb = Sa + TBM * LDT;
    #pragma unroll
    for (int i = 0; i < 4; i++) {
        int ch = tid + i * 256, r = ch >> 3, c = ch & 7;
        cpasync16(Sa + r * LDT + c * 8, Ab + (size_t)r * Hh + k0 + c * 8);
    }
    #pragma unroll
    for (int i = 0; i < 8; i++) {
        int ch = tid + i * 256, r = ch >> 3, c = ch & 7;
        cpasync16(Sb + r * LDT + c * 8, Wb + (size_t)r * Hh + k0 + c * 8);
    }
    cp_commit();
}

__global__ __launch_bounds__(256, 1) void gemm_mma(
    const bf16* __restrict__ A, const bf16* __restrict__ W,
    const float* __restrict__ bias, const float* __restrict__ resid,
    void* __restrict__ outv, float scale, int mode)
{
    extern __shared__ bf16 smb[];
    const int tid = threadIdx.x, warp = tid >> 5, lane = tid & 31;
    const int wm = warp >> 2;
    const int wn = warp & 3;
    const int bn = blockIdx.x, bm = blockIdx.y;

    const bf16* Ab = A + (size_t)(bm * TBM) * Hh;
    const bf16* Wb = W + (size_t)(bn * TBN) * Hh;

    float acc[4][8][4];
    #pragma unroll
    for (int i = 0; i < 4; i++)
        #pragma unroll
        for (int j = 0; j < 8; j++)
            #pragma unroll
            for (int e = 0; e < 4; e++) acc[i][j][e] = 0.0f;

    load_stage(smb, Ab, Wb, 0, 0, tid);
    load_stage(smb, Ab, Wb, 1, TKC, tid);
    load_stage(smb, Ab, Wb, 2, 2 * TKC, tid);

    const int a_row = (lane & 15);
    const int a_kof = (lane >> 4) * 8;
    const int b_row = (lane & 7) + ((lane >> 4) * 8);
    const int b_kof = ((lane >> 3) & 1) * 8;

    uint32_t af[2][4][4];
    uint32_t bfr[2][8][2];

    #pragma unroll 1
    for (int kt = 0; kt < NKI; kt++) {
        // guarantee stages kt AND kt+1 resident (cross-chunk prefetch target)
        if (kt < NKI - 2) cp_wait1();
        else              cp_wait0();
        __syncthreads();                 // visibility + protect stage kt-1 overwrite
        if (kt + 3 < NKI)
            load_stage(smb, Ab, Wb, (kt + 3) & 3, (kt + 3) * TKC, tid);

        const bf16* Sa = smb + (size_t)(kt & 3) * STG_HALVES;
        const bf16* Sb = Sa + TBM * LDT;

        if (kt == 0) {                   // one-time prime of buffer 0
            #pragma unroll
            for (int i = 0; i < 4; i++)
                ldsm4(af[0][i][0], af[0][i][1], af[0][i][2], af[0][i][3],
                      Sa + (wm*64 + i*16 + a_row) * LDT + a_kof);
            #pragma unroll
            for (int j = 0; j < 4; j++) {
                uint32_t r0, r1, r2, r3;
                ldsm4(r0, r1, r2, r3,
                      Sb + (wn*64 + j*16 + b_row) * LDT + b_kof);
                bfr[0][j*2  ][0] = r0; bfr[0][j*2  ][1] = r1;
                bfr[0][j*2+1][0] = r2; bfr[0][j*2+1][1] = r3;
            }
        }

        #pragma unroll
        for (int s = 0; s < TKC / 16; s++) {
            const int cb = s & 1, nb = cb ^ 1;
            // prefetch next k16 (crosses into stage kt+1 at s==3)
            if (s < 3) {
                const int ks = (s + 1) * 16;
                #pragma unroll
                for (int i = 0; i < 4; i++)
                    ldsm4(af[nb][i][0], af[nb][i][1], af[nb][i][2], af[nb][i][3],
                          Sa + (wm*64 + i*16 + a_row) * LDT + ks + a_kof);
                #pragma unroll
                for (int j = 0; j < 4; j++) {
                    uint32_t r0, r1, r2, r3;
                    ldsm4(r0, r1, r2, r3,
                          Sb + (wn*64 + j*16 + b_row) * LDT + ks + b_kof);
                    bfr[nb][j*2  ][0] = r0; bfr[nb][j*2  ][1] = r1;
                    bfr[nb][j*2+1][0] = r2; bfr[nb][j*2+1][1] = r3;
                }
            } else if (kt + 1 < NKI) {
                const bf16* Na = smb + (size_t)((kt + 1) & 3) * STG_HALVES;
                const bf16* Nb = Na + TBM * LDT;
                #pragma unroll
                for (int i = 0; i < 4; i++)
                    ldsm4(af[nb][i][0], af[nb][i][1], af[nb][i][2], af[nb][i][3],
                          Na + (wm*64 + i*16 + a_row) * LDT + a_kof);
                #pragma unroll
                for (int j = 0; j < 4; j++) {
                    uint32_t r0, r1, r2, r3;
                    ldsm4(r0, r1, r2, r3,
                          Nb + (wn*64 + j*16 + b_row) * LDT + b_kof);
                    bfr[nb][j*2  ][0] = r0; bfr[nb][j*2  ][1] = r1;
                    bfr[nb][j*2+1][0] = r2; bfr[nb][j*2+1][1] = r3;
                }
            }
            #pragma unroll
            for (int i = 0; i < 4; i++)
                #pragma unroll
                for (int j = 0; j < 8; j++)
                    mma16816(acc[i][j], af[cb][i], bfr[cb][j]);
        }
    }

    // ---- register epilogue ----
    bf16*  outb = (bf16*)outv;
    float* outf = (float*)outv;
    const int mbase = bm * TBM + wm * 64 + (lane >> 2);
    const int nbase = bn * TBN + wn * 64 + (lane & 3) * 2;
    #pragma unroll
    for (int i = 0; i < 4; i++) {
        #pragma unroll
        for (int j = 0; j < 8; j++) {
            const int n = nbase + j * 8;
            const float b0 = bias[n], b1 = bias[n + 1];
            #pragma unroll
            for (int half = 0; half < 2; half++) {
                const int m = mbase + i * 16 + half * 8;
                float v0 = (acc[i][j][half*2]     + b0) * scale;
                float v1 = (acc[i][j][half*2 + 1] + b1) * scale;
                if (mode == 0) {
                    __nv_bfloat162 p = __floats2bfloat162_rn(v0, v1);
                    *(__nv_bfloat162*)(outb + (size_t)m * Hh + n) = p;
                } else {
                    const float* rp = resid + (size_t)m * Hh + n;
                    float2 o; o.x = v0 + rp[0]; o.y = v1 + rp[1];
                    *(float2*)(outf + (size_t)m * Hh + n) = o;
                }
            }
        }
    }
}

// ============================================================================
// Flash cross-attention v3 — unchanged from round 7
// ============================================================================
#define LDK 136
#define LDP2 72
#define ATTN3_SMEM ((64*LDK + 2*2*64*LDK + 64*LDP2)*2 + 3*128*4)   // 97792

__global__ __launch_bounds__(256, 2) void attn3(
    const bf16* __restrict__ Q, const bf16* __restrict__ K,
    const bf16* __restrict__ V, const int* __restrict__ amask,
    bf16* __restrict__ ctx)
{
    extern __shared__ char smr[];
    bf16*  Qs  = (bf16*)smr;
    bf16*  KVs = Qs + 64*LDK;
    bf16*  Ps  = KVs + 2*2*64*LDK;
    float* pm    = (float*)(Ps + 64*LDP2);
    float* psum  = pm + 128;
    float* sbias = psum + 128;

    const int tid = threadIdx.x, warp = tid >> 5, lane = tid & 31;
    const int wm = warp >> 1;
    const int wn = warp & 1;
    const int b = blockIdx.y >> 5, h = blockIdx.y & 31;
    const int lt = blockIdx.x;

    const int r0 = lane >> 2;
    const int qp = lane & 3;
    const int a_row = lane & 15;
    const int a_kof = (lane >> 4) * 8;
    const int b_row = (lane & 7) + ((lane >> 4) * 8);
    const int b_kof = ((lane >> 3) & 1) * 8;

    const bf16* Qb = Q + ((size_t)(b*Lq + lt*64)) * Hh + h*HDd;
    #pragma unroll
    for (int e = tid; e < 64*16; e += 256) {
        int r = e >> 4, c = (e & 15) * 8;
        *(uint4*)(Qs + r*LDK + c) = *(const uint4*)(Qb + (size_t)r*Hh + c);
    }
    {
        bf16* Ks0 = KVs;
        bf16* Vs0 = KVs + 64*LDK;
        const bf16* Kb = K + ((size_t)(b*Vn)) * Hh + h*HDd;
        const bf16* Vb = V + ((size_t)(b*Vn)) * Hh + h*HDd;
        #pragma unroll
        for (int i = 0; i < 4; i++) {
            int ch = tid + i * 256, r = ch >> 4, c = (ch & 15) * 8;
            cpasync16(Ks0 + r*LDK + c, Kb + (size_t)r*Hh + c);
        }
        #pragma unroll
        for (int i = 0; i < 4; i++) {
            int ch = tid + i * 256, r = ch >> 4, c = (ch & 15) * 8;
            cpasync16(Vs0 + r*LDK + c, Vb + (size_t)r*Hh + c);
        }
        cp_commit();
        if (tid < 64) sbias[tid] = amask[b*Vn + tid] ? 0.0f : -1e30f;
    }
    __syncthreads();

    uint32_t qa[8][4];
    #pragma unroll
    for (int k = 0; k < 8; k++)
        ldsm4(qa[k][0], qa[k][1], qa[k][2], qa[k][3],
              Qs + (wm*16 + a_row) * LDK + k*16 + a_kof);

    float oacc[8][4];
    #pragma unroll
    for (int j = 0; j < 8; j++)
        #pragma unroll
        for (int e = 0; e < 4; e++) oacc[j][e] = 0.0f;
    float mrun0 = -1e30f, mrun1 = -1e30f, l0 = 0.0f, l1 = 0.0f;

    #pragma unroll 1
    for (int jt = 0; jt < Vn/64; jt++) {
        const int st = jt & 1;
        cp_wait0();
        __syncthreads();

        if (jt + 1 < Vn/64) {
            const int ns = st ^ 1;
            bf16* Ksn = KVs + ns*2*64*LDK;
            bf16* Vsn = Ksn + 64*LDK;
            const bf16* Kb = K + ((size_t)(b*Vn + (jt+1)*64)) * Hh + h*HDd;
            const bf16* Vb = V + ((size_t)(b*Vn + (jt+1)*64)) * Hh + h*HDd;
            #pragma unroll
            for (int i = 0; i < 4; i++) {
                int ch = tid + i * 256, r = ch >> 4, c = (ch & 15) * 8;
                cpasync16(Ksn + r*LDK + c, Kb + (size_t)r*Hh + c);
            }
            #pragma unroll
            for (int i = 0; i < 4; i++) {
                int ch = tid + i * 256, r = ch >> 4, c = (ch & 15) * 8;
                cpasync16(Vsn + r*LDK + c, Vb + (size_t)r*Hh + c);
            }
            cp_commit();
            if (tid < 64) sbias[(st^1)*64 + tid] =
                amask[b*Vn + (jt+1)*64 + tid] ? 0.0f : -1e30f;
        }

        const bf16* Ksb = KVs + st*2*64*LDK;
        const bf16* Vsb = Ksb + 64*LDK;

        float sacc[4][4];
        #pragma unroll
        for (int t = 0; t < 4; t++)
            #pragma unroll
            for (int e = 0; e < 4; e++) sacc[t][e] = 0.0f;
        #pragma unroll
        for (int k = 0; k < 8; k++) {
            #pragma unroll
            for (int g = 0; g < 2; g++) {
                uint32_t u0, u1, u2, u3;
                ldsm4(u0, u1, u2, u3,
                      Ksb + (wn*32 + g*16 + b_row) * LDK + k*16 + b_kof);
                uint32_t bb0[2] = {u0, u1}, bb1[2] = {u2, u3};
                mma16816(sacc[g*2  ], qa[k], bb0);
                mma16816(sacc[g*2+1], qa[k], bb1);
            }
        }

        float m0 = -1e30f, m1 = -1e30f;
        #pragma unroll
        for (int t = 0; t < 4; t++) {
            const int c0 = wn*32 + t*8 + qp*2;
            float bi0 = sbias[st*64 + c0], bi1 = sbias[st*64 + c0 + 1];
            sacc[t][0] += bi0; sacc[t][1] += bi1;
            sacc[t][2] += bi0; sacc[t][3] += bi1;
            m0 = fmaxf(m0, fmaxf(sacc[t][0], sacc[t][1]));
            m1 = fmaxf(m1, fmaxf(sacc[t][2], sacc[t][3]));
        }
        m0 = fmaxf(m0, __shfl_xor_sync(0xffffffffu, m0, 1));
        m0 = fmaxf(m0, __shfl_xor_sync(0xffffffffu, m0, 2));
        m1 = fmaxf(m1, __shfl_xor_sync(0xffffffffu, m1, 1));
        m1 = fmaxf(m1, __shfl_xor_sync(0xffffffffu, m1, 2));
        if (qp == 0) {
            pm[wn*64 + wm*16 + r0]     = m0;
            pm[wn*64 + wm*16 + r0 + 8] = m1;
        }
        __syncthreads();
        float mt0 = fmaxf(m0, pm[(wn^1)*64 + wm*16 + r0]);
        float mt1 = fmaxf(m1, pm[(wn^1)*64 + wm*16 + r0 + 8]);
        float mn0 = fmaxf(mrun0, mt0), mn1 = fmaxf(mrun1, mt1);
        float al0 = __expf(mrun0 - mn0), al1 = __expf(mrun1 - mn1);
        mrun0 = mn0; mrun1 = mn1;

        float s0 = 0.0f, s1 = 0.0f;
        #pragma unroll
        for (int t = 0; t < 4; t++) {
            float p00 = __expf(sacc[t][0] - mn0), p01 = __expf(sacc[t][1] - mn0);
            float p10 = __expf(sacc[t][2] - mn1), p11 = __expf(sacc[t][3] - mn1);
            s0 += p00 + p01; s1 += p10 + p11;
            __nv_bfloat162 w0 = __floats2bfloat162_rn(p00, p01);
            __nv_bfloat162 w1 = __floats2bfloat162_rn(p10, p11);
            const int c0 = wn*32 + t*8 + qp*2;
            *(__nv_bfloat162*)(Ps + (wm*16 + r0)     * LDP2 + c0) = w0;
            *(__nv_bfloat162*)(Ps + (wm*16 + r0 + 8) * LDP2 + c0) = w1;
        }
        s0 += __shfl_xor_sync(0xffffffffu, s0, 1);
        s0 += __shfl_xor_sync(0xffffffffu, s0, 2);
        s1 += __shfl_xor_sync(0xffffffffu, s1, 1);
        s1 += __shfl_xor_sync(0xffffffffu, s1, 2);
        if (qp == 0) {
            psum[wn*64 + wm*16 + r0]     = s0;
            psum[wn*64 + wm*16 + r0 + 8] = s1;
        }
        #pragma unroll
        for (int j = 0; j < 8; j++) {
            oacc[j][0] *= al0; oacc[j][1] *= al0;
            oacc[j][2] *= al1; oacc[j][3] *= al1;
        }
        l0 *= al0; l1 *= al1;
        __syncthreads();
        l0 += psum[wm*16 + r0]     + psum[64 + wm*16 + r0];
        l1 += psum[wm*16 + r0 + 8] + psum[64 + wm*16 + r0 + 8];

        uint32_t pa[4][4];
        #pragma unroll
        for (int kt = 0; kt < 4; kt++)
            ldsm4(pa[kt][0], pa[kt][1], pa[kt][2], pa[kt][3],
                  Ps + (wm*16 + a_row) * LDP2 + kt*16 + a_kof);
        #pragma unroll
        for (int kt = 0; kt < 4; kt++) {
            #pragma unroll
            for (int g = 0; g < 4; g++) {
                uint32_t u0, u1, u2, u3;
                ldsm4t(u0, u1, u2, u3,
                       Vsb + (kt*16 + a_row) * LDK + wn*64 + g*16 + a_kof);
                uint32_t bb0[2] = {u0, u1}, bb1[2] = {u2, u3};
                mma16816(oacc[g*2  ], pa[kt], bb0);
                mma16816(oacc[g*2+1], pa[kt], bb1);
            }
        }
    }

    const float i0 = 1.0f / l0, i1 = 1.0f / l1;
    bf16* Cb = ctx + ((size_t)(b*Lq + lt*64 + wm*16)) * Hh + h*HDd;
    #pragma unroll
    for (int j = 0; j < 8; j++) {
        const int n = wn*64 + j*8 + qp*2;
        __nv_bfloat162 w0 = __floats2bfloat162_rn(oacc[j][0]*i0, oacc[j][1]*i0);
        __nv_bfloat162 w1 = __floats2bfloat162_rn(oacc[j][2]*i1, oacc[j][3]*i1);
        *(__nv_bfloat162*)(Cb + (size_t)(r0)     * Hh + n) = w0;
        *(__nv_bfloat162*)(Cb + (size_t)(r0 + 8) * Hh + n) = w1;
    }
}

// ============================================================================
// LayerNorm over last dim (4096) per row
// ============================================================================
__global__ __launch_bounds__(256) void ln_kernel(
    const float* __restrict__ X, const float* __restrict__ g,
    const float* __restrict__ be, float* __restrict__ out)
{
    __shared__ float red[20];
    const int row = blockIdx.x, tid = threadIdx.x;
    const float* x = X + (size_t)row * Hh;
    float s = 0.0f, s2 = 0.0f;
    for (int i = tid; i < Hh; i += 256) { float v = x[i]; s += v; s2 += v*v; }
    #pragma unroll
    for (int o = 16; o; o >>= 1) {
        s  += __shfl_xor_sync(0xffffffffu, s,  o);
        s2 += __shfl_xor_sync(0xffffffffu, s2, o);
    }
    if ((tid & 31) == 0) { red[tid >> 5] = s; red[8 + (tid >> 5)] = s2; }
    __syncthreads();
    if (tid < 32) {
        float a = (tid < 8) ? red[tid] : 0.0f;
        float c = (tid < 8) ? red[8 + tid] : 0.0f;
        #pragma unroll
        for (int o = 4; o; o >>= 1) {
            a += __shfl_xor_sync(0xffffffffu, a, o);
            c += __shfl_xor_sync(0xffffffffu, c, o);
        }
        if (tid == 0) { red[16] = a; red[17] = c; }
    }
    __syncthreads();
    const float mu  = red[16] * (1.0f / Hh);
    const float var = red[17] * (1.0f / Hh) - mu*mu;
    const float inv = rsqrtf(var + 1e-5f);
    for (int i = tid; i < Hh; i += 256)
        out[(size_t)row * Hh + i] = (x[i] - mu) * inv * g[i] + be[i];
}

// ============================================================================
// host launcher
// ============================================================================
extern "C" void kernel_launch(void* const* d_in, const int* in_sizes, int n_in,
                              void* d_out, int out_size)
{
    const float* hidden = (const float*)d_in[0];
    const float* vision = (const float*)d_in[1];
    const int*   amask  = (const int*)  d_in[2];
    const float* Wq = (const float*)d_in[3];
    const float* bq = (const float*)d_in[4];
    const float* Wk = (const float*)d_in[5];
    const float* bk = (const float*)d_in[6];
    const float* Wv = (const float*)d_in[7];
    const float* bv = (const float*)d_in[8];
    const float* Wo = (const float*)d_in[9];
    const float* bo = (const float*)d_in[10];
    const float* lng = (const float*)d_in[11];
    const float* lnb = (const float*)d_in[12];
    float* out = (float*)d_out;

    bf16 *phb, *pvb, *pWq, *pWk, *pWv, *pWo, *pQ, *pK, *pV, *pCtx;
    float *pX;
    cudaGetSymbolAddress((void**)&phb, g_hb);
    cudaGetSymbolAddress((void**)&pvb, g_vb);
    cudaGetSymbolAddress((void**)&pWq, g_Wqb);
    cudaGetSymbolAddress((void**)&pWk, g_Wkb);
    cudaGetSymbolAddress((void**)&pWv, g_Wvb);
    cudaGetSymbolAddress((void**)&pWo, g_Wob);
    cudaGetSymbolAddress((void**)&pQ,  g_Qb);
    cudaGetSymbolAddress((void**)&pK,  g_Kb);
    cudaGetSymbolAddress((void**)&pV,  g_Vb);
    cudaGetSymbolAddress((void**)&pCtx, g_ctx);
    cudaGetSymbolAddress((void**)&pX,  g_X);

    cudaFuncSetAttribute(gemm_mma, cudaFuncAttributeMaxDynamicSharedMemorySize, GEMM_SMEM);
    cudaFuncSetAttribute(attn3,    cudaFuncAttributeMaxDynamicSharedMemorySize, ATTN3_SMEM);

    const long long total4 = (long long)CONV_TOTAL;
    f2bf_all<<<(unsigned)((total4 + 255) / 256), 256>>>(
        hidden, vision, Wq, Wk, Wv, Wo, phb, pvb, pWq, pWk, pWv, pWo);

    dim3 gb(Hh / TBN, Mrows / TBM);      // (16, 16)
    dim3 tb(256);

    gemm_mma<<<gb, tb, GEMM_SMEM>>>(phb, pWq, bq, nullptr, pQ, QSCALE, 0);
    gemm_mma<<<gb, tb, GEMM_SMEM>>>(pvb, pWk, bk, nullptr, pK, 1.0f, 0);
    gemm_mma<<<gb, tb, GEMM_SMEM>>>(pvb, pWv, bv, nullptr, pV, 1.0f, 0);
    attn3<<<dim3(Lq / 64, Bb * NHh), tb, ATTN3_SMEM>>>(pQ, pK, pV, amask, pCtx);
    gemm_mma<<<gb, tb, GEMM_SMEM>>>(pCtx, pWo, bo, hidden, pX, 1.0f, 2);
    ln_kernel<<<Mrows, tb>>>(pX, lng, lnb, out);
}

// round 13
// speedup vs baseline: 4.8002x; 1.0111x over previous
#include <cuda_runtime.h>
#include <cuda_bf16.h>
#include <math.h>
#include <cstdint>

typedef __nv_bfloat16 bf16;

// ---------------- problem constants ----------------
#define Bb   2
#define Lq   1024
#define Vn   1024
#define Hh   4096
#define NHh  32
#define HDd  128
#define Mrows (Bb*Lq)          // 2048
#define QSCALE 0.08838834764831845f   // 1/sqrt(128)

#define A4n ((long long)Mrows*Hh/4)   // 2M float4
#define W4n ((long long)Hh*Hh/4)      // 4M float4

// ---------------- scratch (device globals) ----------------------------------
__device__ bf16  g_hb [(size_t)Mrows*Hh];
__device__ bf16  g_vb [(size_t)Mrows*Hh];
__device__ bf16  g_Wqb[(size_t)Hh*Hh];
__device__ bf16  g_Wkb[(size_t)Hh*Hh];
__device__ bf16  g_Wvb[(size_t)Hh*Hh];
__device__ bf16  g_Wob[(size_t)Hh*Hh];
__device__ bf16  g_Qb [(size_t)Mrows*Hh];
__device__ bf16  g_Kb [(size_t)Mrows*Hh];
__device__ bf16  g_Vb [(size_t)Mrows*Hh];
__device__ bf16  g_ctx[(size_t)Mrows*Hh];
__device__ float g_X  [(size_t)Mrows*Hh];

// ---------------- low-level helpers -----------------------------------------
__device__ __forceinline__ void cpasync16(void* sdst, const void* gsrc) {
    unsigned s = (unsigned)__cvta_generic_to_shared(sdst);
    asm volatile("cp.async.cg.shared.global [%0], [%1], 16;" :: "r"(s), "l"(gsrc));
}
__device__ __forceinline__ void cp_commit() { asm volatile("cp.async.commit_group;"); }
__device__ __forceinline__ void cp_wait1()  { asm volatile("cp.async.wait_group 1;"); }
__device__ __forceinline__ void cp_wait0()  { asm volatile("cp.async.wait_group 0;"); }

__device__ __forceinline__ void ldsm4(uint32_t& r0, uint32_t& r1, uint32_t& r2, uint32_t& r3,
                                      const void* p) {
    unsigned a = (unsigned)__cvta_generic_to_shared(p);
    asm volatile("ldmatrix.sync.aligned.m8n8.x4.shared.b16 {%0,%1,%2,%3}, [%4];"
                 : "=r"(r0), "=r"(r1), "=r"(r2), "=r"(r3) : "r"(a));
}
__device__ __forceinline__ void ldsm4t(uint32_t& r0, uint32_t& r1, uint32_t& r2, uint32_t& r3,
                                       const void* p) {
    unsigned a = (unsigned)__cvta_generic_to_shared(p);
    asm volatile("ldmatrix.sync.aligned.m8n8.x4.trans.shared.b16 {%0,%1,%2,%3}, [%4];"
                 : "=r"(r0), "=r"(r1), "=r"(r2), "=r"(r3) : "r"(a));
}

__device__ __forceinline__ void mma16816(float* c, const uint32_t* a, const uint32_t* b) {
    asm volatile(
        "mma.sync.aligned.m16n8k16.row.col.f32.bf16.bf16.f32 "
        "{%0,%1,%2,%3}, {%4,%5,%6,%7}, {%8,%9}, {%0,%1,%2,%3};"
        : "+f"(c[0]), "+f"(c[1]), "+f"(c[2]), "+f"(c[3])
        : "r"(a[0]), "r"(a[1]), "r"(a[2]), "r"(a[3]), "r"(b[0]), "r"(b[1]));
}

__device__ __forceinline__ void cvt_one(const float4* s, uint2* d, size_t i) {
    float4 x = s[i];
    __nv_bfloat162 a = __floats2bfloat162_rn(x.x, x.y);
    __nv_bfloat162 b = __floats2bfloat162_rn(x.z, x.w);
    uint2 p; p.x = *(unsigned*)&a; p.y = *(unsigned*)&b;
    d[i] = p;
}

// ============================================================================
// standalone fp32 -> bf16 conversion for up to two tensors
// ============================================================================
__global__ __launch_bounds__(256) void f2bf2(
    const float* __restrict__ s0, bf16* __restrict__ d0, long long n0,
    const float* __restrict__ s1, bf16* __restrict__ d1, long long n1)
{
    long long i = ((long long)blockIdx.x * 256 + threadIdx.x) * 2;
    #pragma unroll
    for (int u = 0; u < 2; u++) {
        long long j = i + u;
        if (j < n0)            cvt_one((const float4*)s0, (uint2*)d0, (size_t)j);
        else if (j - n0 < n1)  cvt_one((const float4*)s1, (uint2*)d1, (size_t)(j - n0));
    }
}

// ============================================================================
// mma.sync bf16 GEMM: out = (A[M,K] @ W[N,K]^T + bias) * scale (+resid)
// CTA tile 128x256, BK=64, NST=4 cp.async stages, 8 warps (2x4), warp 64x64.
// Flat k16 pipeline with cross-chunk fragment prefetch.
// Extra blocks (blockIdx.y >= 16) run fp32->bf16 conversion for the NEXT
// launch's operands, filling wave-2 idle SMs (conv CTAs co-schedule 8/SM).
// ============================================================================
#define TBM 128
#define TBN 256
#define TKC 64
#define NST 4
#define LDT 72
#define STG_HALVES ((TBM+TBN)*LDT)              // 27648
#define GEMM_SMEM (NST*STG_HALVES*2)            // 221184 bytes
#define NKI (Hh / TKC)                          // 64
#define CONV_ROWS 20                            // 20*16 = 320 conv blocks

__device__ __forceinline__ void load_stage(bf16* smb, const bf16* Ab, const bf16* Wb,
                                           int slot, int k0, int tid)
{
    bf16* Sa = smb + (size_t)slot * STG_HALVES;
    bf16* Sb = Sa + TBM * LDT;
    #pragma unroll
    for (int i = 0; i < 4; i++) {
        int ch = tid + i * 256, r = ch >> 3, c = ch & 7;
        cpasync16(Sa + r * LDT + c * 8, Ab + (size_t)r * Hh + k0 + c * 8);
    }
    #pragma unroll
    for (int i = 0; i < 8; i++) {
        int ch = tid + i * 256, r = ch >> 3, c = ch & 7;
        cpasync16(Sb + r * LDT + c * 8, Wb + (size_t)r * Hh + k0 + c * 8);
    }
    cp_commit();
}

__global__ __launch_bounds__(256, 1) void gemm_mma(
    const bf16* __restrict__ A, const bf16* __restrict__ W,
    const float* __restrict__ bias, const float* __restrict__ resid,
    void* __restrict__ outv, float scale, int mode,
    const float* __restrict__ csrc0, bf16* __restrict__ cdst0, long long cn0,
    const float* __restrict__ csrc1, bf16* __restrict__ cdst1, long long cn1)
{
    const int tid = threadIdx.x;

    // ---- conversion blocks (fill idle wave-2 SMs) ----
    if (blockIdx.y >= 16) {
        const int c = (blockIdx.y - 16) * gridDim.x + blockIdx.x;
        const long long CB = (long long)(gridDim.y - 16) * gridDim.x;
        const long long stride = CB * 256;
        if (csrc0)
            for (long long i = (long long)c * 256 + tid; i < cn0; i += stride)
                cvt_one((const float4*)csrc0, (uint2*)cdst0, (size_t)i);
        if (csrc1)
            for (long long i = (long long)c * 256 + tid; i < cn1; i += stride)
                cvt_one((const float4*)csrc1, (uint2*)cdst1, (size_t)i);
        return;
    }

    extern __shared__ bf16 smb[];
    const int warp = tid >> 5, lane = tid & 31;
    const int wm = warp >> 2;
    const int wn = warp & 3;
    const int bn = blockIdx.x, bm = blockIdx.y;

    const bf16* Ab = A + (size_t)(bm * TBM) * Hh;
    const bf16* Wb = W + (size_t)(bn * TBN) * Hh;

    float acc[4][8][4];
    #pragma unroll
    for (int i = 0; i < 4; i++)
        #pragma unroll
        for (int j = 0; j < 8; j++)
            #pragma unroll
            for (int e = 0; e < 4; e++) acc[i][j][e] = 0.0f;

    load_stage(smb, Ab, Wb, 0, 0, tid);
    load_stage(smb, Ab, Wb, 1, TKC, tid);
    load_stage(smb, Ab, Wb, 2, 2 * TKC, tid);

    const int a_row = (lane & 15);
    const int a_kof = (lane >> 4) * 8;
    const int b_row = (lane & 7) + ((lane >> 4) * 8);
    const int b_kof = ((lane >> 3) & 1) * 8;

    uint32_t af[2][4][4];
    uint32_t bfr[2][8][2];

    #pragma unroll 1
    for (int kt = 0; kt < NKI; kt++) {
        if (kt < NKI - 2) cp_wait1();
        else              cp_wait0();
        __syncthreads();
        if (kt + 3 < NKI)
            load_stage(smb, Ab, Wb, (kt + 3) & 3, (kt + 3) * TKC, tid);

        const bf16* Sa = smb + (size_t)(kt & 3) * STG_HALVES;
        const bf16* Sb = Sa + TBM * LDT;

        if (kt == 0) {
            #pragma unroll
            for (int i = 0; i < 4; i++)
                ldsm4(af[0][i][0], af[0][i][1], af[0][i][2], af[0][i][3],
                      Sa + (wm*64 + i*16 + a_row) * LDT + a_kof);
            #pragma unroll
            for (int j = 0; j < 4; j++) {
                uint32_t r0, r1, r2, r3;
                ldsm4(r0, r1, r2, r3,
                      Sb + (wn*64 + j*16 + b_row) * LDT + b_kof);
                bfr[0][j*2  ][0] = r0; bfr[0][j*2  ][1] = r1;
                bfr[0][j*2+1][0] = r2; bfr[0][j*2+1][1] = r3;
            }
        }

        #pragma unroll
        for (int s = 0; s < TKC / 16; s++) {
            const int cb = s & 1, nb = cb ^ 1;
            if (s < 3) {
                const int ks = (s + 1) * 16;
                #pragma unroll
                for (int i = 0; i < 4; i++)
                    ldsm4(af[nb][i][0], af[nb][i][1], af[nb][i][2], af[nb][i][3],
                          Sa + (wm*64 + i*16 + a_row) * LDT + ks + a_kof);
                #pragma unroll
                for (int j = 0; j < 4; j++) {
                    uint32_t r0, r1, r2, r3;
                    ldsm4(r0, r1, r2, r3,
                          Sb + (wn*64 + j*16 + b_row) * LDT + ks + b_kof);
                    bfr[nb][j*2  ][0] = r0; bfr[nb][j*2  ][1] = r1;
                    bfr[nb][j*2+1][0] = r2; bfr[nb][j*2+1][1] = r3;
                }
            } else if (kt + 1 < NKI) {
                const bf16* Na = smb + (size_t)((kt + 1) & 3) * STG_HALVES;
                const bf16* Nb = Na + TBM * LDT;
                #pragma unroll
                for (int i = 0; i < 4; i++)
                    ldsm4(af[nb][i][0], af[nb][i][1], af[nb][i][2], af[nb][i][3],
                          Na + (wm*64 + i*16 + a_row) * LDT + a_kof);
                #pragma unroll
                for (int j = 0; j < 4; j++) {
                    uint32_t r0, r1, r2, r3;
                    ldsm4(r0, r1, r2, r3,
                          Nb + (wn*64 + j*16 + b_row) * LDT + b_kof);
                    bfr[nb][j*2  ][0] = r0; bfr[nb][j*2  ][1] = r1;
                    bfr[nb][j*2+1][0] = r2; bfr[nb][j*2+1][1] = r3;
                }
            }
            #pragma unroll
            for (int i = 0; i < 4; i++)
                #pragma unroll
                for (int j = 0; j < 8; j++)
                    mma16816(acc[i][j], af[cb][i], bfr[cb][j]);
        }
    }

    // ---- register epilogue ----
    bf16*  outb = (bf16*)outv;
    float* outf = (float*)outv;
    const int mbase = bm * TBM + wm * 64 + (lane >> 2);
    const int nbase = bn * TBN + wn * 64 + (lane & 3) * 2;
    #pragma unroll
    for (int i = 0; i < 4; i++) {
        #pragma unroll
        for (int j = 0; j < 8; j++) {
            const int n = nbase + j * 8;
            const float b0 = bias[n], b1 = bias[n + 1];
            #pragma unroll
            for (int half = 0; half < 2; half++) {
                const int m = mbase + i * 16 + half * 8;
                float v0 = (acc[i][j][half*2]     + b0) * scale;
                float v1 = (acc[i][j][half*2 + 1] + b1) * scale;
                if (mode == 0) {
                    __nv_bfloat162 p = __floats2bfloat162_rn(v0, v1);
                    *(__nv_bfloat162*)(outb + (size_t)m * Hh + n) = p;
                } else {
                    const float* rp = resid + (size_t)m * Hh + n;
                    float2 o; o.x = v0 + rp[0]; o.y = v1 + rp[1];
                    *(float2*)(outf + (size_t)m * Hh + n) = o;
                }
            }
        }
    }
}

// ============================================================================
// Flash cross-attention v3 — unchanged
// ============================================================================
#define LDK 136
#define LDP2 72
#define ATTN3_SMEM ((64*LDK + 2*2*64*LDK + 64*LDP2)*2 + 3*128*4)   // 97792

__global__ __launch_bounds__(256, 2) void attn3(
    const bf16* __restrict__ Q, const bf16* __restrict__ K,
    const bf16* __restrict__ V, const int* __restrict__ amask,
    bf16* __restrict__ ctx)
{
    extern __shared__ char smr[];
    bf16*  Qs  = (bf16*)smr;
    bf16*  KVs = Qs + 64*LDK;
    bf16*  Ps  = KVs + 2*2*64*LDK;
    float* pm    = (float*)(Ps + 64*LDP2);
    float* psum  = pm + 128;
    float* sbias = psum + 128;

    const int tid = threadIdx.x, warp = tid >> 5, lane = tid & 31;
    const int wm = warp >> 1;
    const int wn = warp & 1;
    const int b = blockIdx.y >> 5, h = blockIdx.y & 31;
    const int lt = blockIdx.x;

    const int r0 = lane >> 2;
    const int qp = lane & 3;
    const int a_row = lane & 15;
    const int a_kof = (lane >> 4) * 8;
    const int b_row = (lane & 7) + ((lane >> 4) * 8);
    const int b_kof = ((lane >> 3) & 1) * 8;

    const bf16* Qb = Q + ((size_t)(b*Lq + lt*64)) * Hh + h*HDd;
    #pragma unroll
    for (int e = tid; e < 64*16; e += 256) {
        int r = e >> 4, c = (e & 15) * 8;
        *(uint4*)(Qs + r*LDK + c) = *(const uint4*)(Qb + (size_t)r*Hh + c);
    }
    {
        bf16* Ks0 = KVs;
        bf16* Vs0 = KVs + 64*LDK;
        const bf16* Kb = K + ((size_t)(b*Vn)) * Hh + h*HDd;
        const bf16* Vb = V + ((size_t)(b*Vn)) * Hh + h*HDd;
        #pragma unroll
        for (int i = 0; i < 4; i++) {
            int ch = tid + i * 256, r = ch >> 4, c = (ch & 15) * 8;
            cpasync16(Ks0 + r*LDK + c, Kb + (size_t)r*Hh + c);
        }
        #pragma unroll
        for (int i = 0; i < 4; i++) {
            int ch = tid + i * 256, r = ch >> 4, c = (ch & 15) * 8;
            cpasync16(Vs0 + r*LDK + c, Vb + (size_t)r*Hh + c);
        }
        cp_commit();
        if (tid < 64) sbias[tid] = amask[b*Vn + tid] ? 0.0f : -1e30f;
    }
    __syncthreads();

    uint32_t qa[8][4];
    #pragma unroll
    for (int k = 0; k < 8; k++)
        ldsm4(qa[k][0], qa[k][1], qa[k][2], qa[k][3],
              Qs + (wm*16 + a_row) * LDK + k*16 + a_kof);

    float oacc[8][4];
    #pragma unroll
    for (int j = 0; j < 8; j++)
        #pragma unroll
        for (int e = 0; e < 4; e++) oacc[j][e] = 0.0f;
    float mrun0 = -1e30f, mrun1 = -1e30f, l0 = 0.0f, l1 = 0.0f;

    #pragma unroll 1
    for (int jt = 0; jt < Vn/64; jt++) {
        const int st = jt & 1;
        cp_wait0();
        __syncthreads();

        if (jt + 1 < Vn/64) {
            const int ns = st ^ 1;
            bf16* Ksn = KVs + ns*2*64*LDK;
            bf16* Vsn = Ksn + 64*LDK;
            const bf16* Kb = K + ((size_t)(b*Vn + (jt+1)*64)) * Hh + h*HDd;
            const bf16* Vb = V + ((size_t)(b*Vn + (jt+1)*64)) * Hh + h*HDd;
            #pragma unroll
            for (int i = 0; i < 4; i++) {
                int ch = tid + i * 256, r = ch >> 4, c = (ch & 15) * 8;
                cpasync16(Ksn + r*LDK + c, Kb + (size_t)r*Hh + c);
            }
            #pragma unroll
            for (int i = 0; i < 4; i++) {
                int ch = tid + i * 256, r = ch >> 4, c = (ch & 15) * 8;
                cpasync16(Vsn + r*LDK + c, Vb + (size_t)r*Hh + c);
            }
            cp_commit();
            if (tid < 64) sbias[(st^1)*64 + tid] =
                amask[b*Vn + (jt+1)*64 + tid] ? 0.0f : -1e30f;
        }

        const bf16* Ksb = KVs + st*2*64*LDK;
        const bf16* Vsb = Ksb + 64*LDK;

        float sacc[4][4];
        #pragma unroll
        for (int t = 0; t < 4; t++)
            #pragma unroll
            for (int e = 0; e < 4; e++) sacc[t][e] = 0.0f;
        #pragma unroll
        for (int k = 0; k < 8; k++) {
            #pragma unroll
            for (int g = 0; g < 2; g++) {
                uint32_t u0, u1, u2, u3;
                ldsm4(u0, u1, u2, u3,
                      Ksb + (wn*32 + g*16 + b_row) * LDK + k*16 + b_kof);
                uint32_t bb0[2] = {u0, u1}, bb1[2] = {u2, u3};
                mma16816(sacc[g*2  ], qa[k], bb0);
                mma16816(sacc[g*2+1], qa[k], bb1);
            }
        }

        float m0 = -1e30f, m1 = -1e30f;
        #pragma unroll
        for (int t = 0; t < 4; t++) {
            const int c0 = wn*32 + t*8 + qp*2;
            float bi0 = sbias[st*64 + c0], bi1 = sbias[st*64 + c0 + 1];
            sacc[t][0] += bi0; sacc[t][1] += bi1;
            sacc[t][2] += bi0; sacc[t][3] += bi1;
            m0 = fmaxf(m0, fmaxf(sacc[t][0], sacc[t][1]));
            m1 = fmaxf(m1, fmaxf(sacc[t][2], sacc[t][3]));
        }
        m0 = fmaxf(m0, __shfl_xor_sync(0xffffffffu, m0, 1));
        m0 = fmaxf(m0, __shfl_xor_sync(0xffffffffu, m0, 2));
        m1 = fmaxf(m1, __shfl_xor_sync(0xffffffffu, m1, 1));
        m1 = fmaxf(m1, __shfl_xor_sync(0xffffffffu, m1, 2));
        if (qp == 0) {
            pm[wn*64 + wm*16 + r0]     = m0;
            pm[wn*64 + wm*16 + r0 + 8] = m1;
        }
        __syncthreads();
        float mt0 = fmaxf(m0, pm[(wn^1)*64 + wm*16 + r0]);
        float mt1 = fmaxf(m1, pm[(wn^1)*64 + wm*16 + r0 + 8]);
        float mn0 = fmaxf(mrun0, mt0), mn1 = fmaxf(mrun1, mt1);
        float al0 = __expf(mrun0 - mn0), al1 = __expf(mrun1 - mn1);
        mrun0 = mn0; mrun1 = mn1;

        float s0 = 0.0f, s1 = 0.0f;
        #pragma unroll
        for (int t = 0; t < 4; t++) {
            float p00 = __expf(sacc[t][0] - mn0), p01 = __expf(sacc[t][1] - mn0);
            float p10 = __expf(sacc[t][2] - mn1), p11 = __expf(sacc[t][3] - mn1);
            s0 += p00 + p01; s1 += p10 + p11;
            __nv_bfloat162 w0 = __floats2bfloat162_rn(p00, p01);
            __nv_bfloat162 w1 = __floats2bfloat162_rn(p10, p11);
            const int c0 = wn*32 + t*8 + qp*2;
            *(__nv_bfloat162*)(Ps + (wm*16 + r0)     * LDP2 + c0) = w0;
            *(__nv_bfloat162*)(Ps + (wm*16 + r0 + 8) * LDP2 + c0) = w1;
        }
        s0 += __shfl_xor_sync(0xffffffffu, s0, 1);
        s0 += __shfl_xor_sync(0xffffffffu, s0, 2);
        s1 += __shfl_xor_sync(0xffffffffu, s1, 1);
        s1 += __shfl_xor_sync(0xffffffffu, s1, 2);
        if (qp == 0) {
            psum[wn*64 + wm*16 + r0]     = s0;
            psum[wn*64 + wm*16 + r0 + 8] = s1;
        }
        #pragma unroll
        for (int j = 0; j < 8; j++) {
            oacc[j][0] *= al0; oacc[j][1] *= al0;
            oacc[j][2] *= al1; oacc[j][3] *= al1;
        }
        l0 *= al0; l1 *= al1;
        __syncthreads();
        l0 += psum[wm*16 + r0]     + psum[64 + wm*16 + r0];
        l1 += psum[wm*16 + r0 + 8] + psum[64 + wm*16 + r0 + 8];

        uint32_t pa[4][4];
        #pragma unroll
        for (int kt = 0; kt < 4; kt++)
            ldsm4(pa[kt][0], pa[kt][1], pa[kt][2], pa[kt][3],
                  Ps + (wm*16 + a_row) * LDP2 + kt*16 + a_kof);
        #pragma unroll
        for (int kt = 0; kt < 4; kt++) {
            #pragma unroll
            for (int g = 0; g < 4; g++) {
                uint32_t u0, u1, u2, u3;
                ldsm4t(u0, u1, u2, u3,
                       Vsb + (kt*16 + a_row) * LDK + wn*64 + g*16 + a_kof);
                uint32_t bb0[2] = {u0, u1}, bb1[2] = {u2, u3};
                mma16816(oacc[g*2  ], pa[kt], bb0);
                mma16816(oacc[g*2+1], pa[kt], bb1);
            }
        }
    }

    const float i0 = 1.0f / l0, i1 = 1.0f / l1;
    bf16* Cb = ctx + ((size_t)(b*Lq + lt*64 + wm*16)) * Hh + h*HDd;
    #pragma unroll
    for (int j = 0; j < 8; j++) {
        const int n = wn*64 + j*8 + qp*2;
        __nv_bfloat162 w0 = __floats2bfloat162_rn(oacc[j][0]*i0, oacc[j][1]*i0);
        __nv_bfloat162 w1 = __floats2bfloat162_rn(oacc[j][2]*i1, oacc[j][3]*i1);
        *(__nv_bfloat162*)(Cb + (size_t)(r0)     * Hh + n) = w0;
        *(__nv_bfloat162*)(Cb + (size_t)(r0 + 8) * Hh + n) = w1;
    }
}

// ============================================================================
// LayerNorm over last dim (4096) per row
// ============================================================================
__global__ __launch_bounds__(256) void ln_kernel(
    const float* __restrict__ X, const float* __restrict__ g,
    const float* __restrict__ be, float* __restrict__ out)
{
    __shared__ float red[20];
    const int row = blockIdx.x, tid = threadIdx.x;
    const float* x = X + (size_t)row * Hh;
    float s = 0.0f, s2 = 0.0f;
    for (int i = tid; i < Hh; i += 256) { float v = x[i]; s += v; s2 += v*v; }
    #pragma unroll
    for (int o = 16; o; o >>= 1) {
        s  += __shfl_xor_sync(0xffffffffu, s,  o);
        s2 += __shfl_xor_sync(0xffffffffu, s2, o);
    }
    if ((tid & 31) == 0) { red[tid >> 5] = s; red[8 + (tid >> 5)] = s2; }
    __syncthreads();
    if (tid < 32) {
        float a = (tid < 8) ? red[tid] : 0.0f;
        float c = (tid < 8) ? red[8 + tid] : 0.0f;
        #pragma unroll
        for (int o = 4; o; o >>= 1) {
            a += __shfl_xor_sync(0xffffffffu, a, o);
            c += __shfl_xor_sync(0xffffffffu, c, o);
        }
        if (tid == 0) { red[16] = a; red[17] = c; }
    }
    __syncthreads();
    const float mu  = red[16] * (1.0f / Hh);
    const float var = red[17] * (1.0f / Hh) - mu*mu;
    const float inv = rsqrtf(var + 1e-5f);
    for (int i = tid; i < Hh; i += 256)
        out[(size_t)row * Hh + i] = (x[i] - mu) * inv * g[i] + be[i];
}

// ============================================================================
// host launcher
// ============================================================================
extern "C" void kernel_launch(void* const* d_in, const int* in_sizes, int n_in,
                              void* d_out, int out_size)
{
    const float* hidden = (const float*)d_in[0];
    const float* vision = (const float*)d_in[1];
    const int*   amask  = (const int*)  d_in[2];
    const float* Wq = (const float*)d_in[3];
    const float* bq = (const float*)d_in[4];
    const float* Wk = (const float*)d_in[5];
    const float* bk = (const float*)d_in[6];
    const float* Wv = (const float*)d_in[7];
    const float* bv = (const float*)d_in[8];
    const float* Wo = (const float*)d_in[9];
    const float* bo = (const float*)d_in[10];
    const float* lng = (const float*)d_in[11];
    const float* lnb = (const float*)d_in[12];
    float* out = (float*)d_out;

    bf16 *phb, *pvb, *pWq, *pWk, *pWv, *pWo, *pQ, *pK, *pV, *pCtx;
    float *pX;
    cudaGetSymbolAddress((void**)&phb, g_hb);
    cudaGetSymbolAddress((void**)&pvb, g_vb);
    cudaGetSymbolAddress((void**)&pWq, g_Wqb);
    cudaGetSymbolAddress((void**)&pWk, g_Wkb);
    cudaGetSymbolAddress((void**)&pWv, g_Wvb);
    cudaGetSymbolAddress((void**)&pWo, g_Wob);
    cudaGetSymbolAddress((void**)&pQ,  g_Qb);
    cudaGetSymbolAddress((void**)&pK,  g_Kb);
    cudaGetSymbolAddress((void**)&pV,  g_Vb);
    cudaGetSymbolAddress((void**)&pCtx, g_ctx);
    cudaGetSymbolAddress((void**)&pX,  g_X);

    cudaFuncSetAttribute(gemm_mma, cudaFuncAttributeMaxDynamicSharedMemorySize, GEMM_SMEM);
    cudaFuncSetAttribute(attn3,    cudaFuncAttributeMaxDynamicSharedMemorySize, ATTN3_SMEM);

    dim3 tb(256);
    // 1) convert only Q-GEMM deps: hidden + Wq
    {
        long long tot = A4n + W4n;                       // 6M float4, 2/thread
        f2bf2<<<(unsigned)((tot + 511) / 512), tb>>>(hidden, phb, A4n, Wq, pWq, W4n);
    }

    dim3 gbc(Hh / TBN, Mrows / TBM + CONV_ROWS);         // (16, 36): gemm + conv blocks
    dim3 gb (Hh / TBN, Mrows / TBM);                     // (16, 16): gemm only

    // 2) Q GEMM + convert(vision, Wk)
    gemm_mma<<<gbc, tb, GEMM_SMEM>>>(phb, pWq, bq, nullptr, pQ, QSCALE, 0,
                                     vision, pvb, A4n, Wk, pWk, W4n);
    // 3) K GEMM + convert(Wv)
    gemm_mma<<<gbc, tb, GEMM_SMEM>>>(pvb, pWk, bk, nullptr, pK, 1.0f, 0,
                                     Wv, pWv, W4n, nullptr, nullptr, 0);
    // 4) V GEMM + convert(Wo)
    gemm_mma<<<gbc, tb, GEMM_SMEM>>>(pvb, pWv, bv, nullptr, pV, 1.0f, 0,
                                     Wo, pWo, W4n, nullptr, nullptr, 0);
    // 5) attention
    attn3<<<dim3(Lq / 64, Bb * NHh), tb, ATTN3_SMEM>>>(pQ, pK, pV, amask, pCtx);
    // 6) O GEMM (+ residual)
    gemm_mma<<<gb, tb, GEMM_SMEM>>>(pCtx, pWo, bo, hidden, pX, 1.0f, 2,
                                    nullptr, nullptr, 0, nullptr, nullptr, 0);
    // 7) LayerNorm
    ln_kernel<<<Mrows, tb>>>(pX, lng, lnb, out);
}